// round 14
// baseline (speedup 1.0000x reference)
#include <cuda_runtime.h>
#include <cuda_bf16.h>
#include <cuda_fp16.h>
#include <math.h>
#include <stdint.h>

// ---------------------------------------------------------------------------
// TCNAttentionBlock. R14: R13 + max-free softmax (exp fused into premix pass
// transiently; sum-only warp scan; no added loop-carried registers).
// N=8, T=1024, E=512, H=8, D=64, P=16.
// ---------------------------------------------------------------------------

#define NB   8
#define TT   1024
#define EE   512
#define HH   8
#define DD   64
#define PP   16
#define LP   1040            // TT + PP
#define LPAD 1088            // attn row padded (17 chunks of 64)
#define KPAD 1152            // K rows padded (9 tiles of 128)
#define SOFTMAX_SCALE 0.044194173824159216f   // 1/sqrt(512)

// ------------------------------ scratch -----------------------------------
__device__ __half g_q  [64 * TT * DD];                     // fp16 [ng][q][64]
__device__ __half g_k  [64 * KPAD * DD];                   // fp16 [ng][l][64]
__device__ __half g_vT [64 * DD * LPAD];                   // fp16 [ng][d][1088]
__device__ __half g_att[(size_t)64 * TT * LP];             // fp16 raw QK^T
__device__ __half g_a  [(size_t)64 * TT * LPAD];           // fp16 attn
__device__ __half g_ctx[NB * TT * EE];                     // fp16
__device__ __half g_h  [NB * TT * EE];                     // fp16 (x + att)
__device__ __half g_t1 [NB * TT * EE];                     // fp16
__device__ float  g_t2 [NB * TT * EE];                     // fp32

// preconverted fp16 weights, layout [chunk][co(512)][64]
__device__ __half g_Wo[8  * 512 * 64];
__device__ __half g_c1[24 * 512 * 64];
__device__ __half g_c2[24 * 512 * 64];

// ---------------------------- PTX helpers ----------------------------------
__device__ __forceinline__ uint32_t smem_u32(const void* p) {
    uint32_t a;
    asm("{ .reg .u64 t; cvta.to.shared.u64 t, %1; cvt.u32.u64 %0, t; }"
        : "=r"(a) : "l"(p));
    return a;
}
#define SWZ(o) ((o) ^ (((o) >> 3) & 0x70))

__device__ __forceinline__ void ldsm4(uint32_t* r, uint32_t addr) {
    asm volatile("ldmatrix.sync.aligned.m8n8.x4.shared.b16 {%0,%1,%2,%3}, [%4];"
                 : "=r"(r[0]), "=r"(r[1]), "=r"(r[2]), "=r"(r[3]) : "r"(addr));
}
__device__ __forceinline__ void mma_f16(float* c, const uint32_t* a, const uint32_t* b) {
    asm volatile(
        "mma.sync.aligned.m16n8k16.row.col.f32.f16.f16.f32 "
        "{%0,%1,%2,%3}, {%4,%5,%6,%7}, {%8,%9}, {%0,%1,%2,%3};"
        : "+f"(c[0]), "+f"(c[1]), "+f"(c[2]), "+f"(c[3])
        : "r"(a[0]), "r"(a[1]), "r"(a[2]), "r"(a[3]), "r"(b[0]), "r"(b[1]));
}
__device__ __forceinline__ void cpasync16(uint32_t saddr, const void* g) {
    asm volatile("cp.async.cg.shared.global [%0], [%1], 16;" :: "r"(saddr), "l"(g));
}
__device__ __forceinline__ void cpasync16z(uint32_t saddr, const void* g, int sz) {
    asm volatile("cp.async.cg.shared.global [%0], [%1], 16, %2;"
                 :: "r"(saddr), "l"(g), "r"(sz));
}
__device__ __forceinline__ void cp_commit() {
    asm volatile("cp.async.commit_group;" ::: "memory");
}
__device__ __forceinline__ void cp_wait0() {
    asm volatile("cp.async.wait_group 0;" ::: "memory");
}
__device__ __forceinline__ void cp_wait1() {
    asm volatile("cp.async.wait_group 1;" ::: "memory");
}
__device__ __forceinline__ uint32_t tf32r_u(float v) {   // for A staging in qkv
    uint32_t u;
    asm("cvt.rna.tf32.f32 %0, %1;" : "=r"(u) : "f"(v));
    return u;
}
__device__ __forceinline__ void mma_tf32(float* c, const uint32_t* a, const uint32_t* b) {
    asm volatile(
        "mma.sync.aligned.m16n8k8.row.col.f32.tf32.tf32.f32 "
        "{%0,%1,%2,%3}, {%4,%5,%6,%7}, {%8,%9}, {%0,%1,%2,%3};"
        : "+f"(c[0]), "+f"(c[1]), "+f"(c[2]), "+f"(c[3])
        : "r"(a[0]), "r"(a[1]), "r"(a[2]), "r"(a[3]), "r"(b[0]), "r"(b[1]));
}

// ---------------------- weight preconversion (fp16) -------------------------
__global__ void conv_w_convert(const float* __restrict__ W, __half* __restrict__ o) {
    int d = blockIdx.x * 256 + threadIdx.x;          // 24*512*64 = 786432
    int c  = d >> 15;
    int co = (d >> 6) & 511;
    int ci = d & 63;
    int tap = c >> 3, cib = (c & 7) << 6;
    o[d] = __float2half(W[(size_t)(co * 512 + cib + ci) * 3 + tap]);
}
__global__ void wo_convert(const float* __restrict__ W, __half* __restrict__ o) {
    int d = blockIdx.x * 256 + threadIdx.x;          // 8*512*64 = 262144
    int c  = d >> 15;
    int co = (d >> 6) & 511;
    int ci = d & 63;
    o[d] = __float2half(W[co * 512 + (c << 6) + ci]);
}

// ------------------------ QKV on tf32 HMMA ----------------------------------
#define QKV_B0 32768
#define QKV_SMEM (32768 + 3 * 16384)
__global__ void __launch_bounds__(256, 2) qkv_hmma_kernel(
    const float* __restrict__ x,
    const float* __restrict__ Wq,
    const float* __restrict__ Wk,
    const float* __restrict__ Wv)
{
    extern __shared__ char smem[];
    const uint32_t sbase = smem_u32(smem);
    const int tid = threadIdx.x;
    const int lane = tid & 31, wid = tid >> 5;
    const int t0 = blockIdx.x * 128;
    const int h  = blockIdx.y;
    const int n  = t0 >> 10;
    const int ng = n * 8 + h;
    const int m0w = (wid & 3) * 32;
    const int n0w = (wid >> 2) * 32;

    #pragma unroll
    for (int it = 0; it < 8; ++it) {
        int lin = it * 1024 + tid * 4;
        int r = lin >> 6, ci = lin & 63;
        float4 v = *(const float4*)(x + (size_t)(t0 + r) * 512 + h * 64 + ci);
        uint32_t off = (ci >> 5) * 16384 + SWZ((uint32_t)(r * 128 + (ci & 31) * 4));
        *(uint4*)(smem + off) = make_uint4(tf32r_u(v.x), tf32r_u(v.y),
                                           tf32r_u(v.z), tf32r_u(v.w));
    }
    #pragma unroll
    for (int m = 0; m < 3; ++m) {
        const float* Wm = (m == 0) ? Wq : (m == 1) ? Wk : Wv;
        #pragma unroll
        for (int it = 0; it < 4; ++it) {
            int lin = it * 1024 + tid * 4;
            int r = lin >> 6, ci = lin & 63;
            float4 v = *(const float4*)(Wm + r * 64 + ci);
            uint32_t off = QKV_B0 + m * 16384 + (ci >> 5) * 8192
                         + SWZ((uint32_t)(r * 128 + (ci & 31) * 4));
            *(uint4*)(smem + off) = make_uint4(tf32r_u(v.x), tf32r_u(v.y),
                                               tf32r_u(v.z), tf32r_u(v.w));
        }
    }
    __syncthreads();

    for (int m = 0; m < 3; ++m) {
        float C[2][4][4];
        #pragma unroll
        for (int mt = 0; mt < 2; ++mt)
            #pragma unroll
            for (int nt = 0; nt < 4; ++nt)
                #pragma unroll
                for (int i = 0; i < 4; ++i) C[mt][nt][i] = 0.f;

        const uint32_t bbase = sbase + QKV_B0 + m * 16384;
        #pragma unroll
        for (int panel = 0; panel < 2; ++panel) {
            #pragma unroll
            for (int ks = 0; ks < 4; ++ks) {
                uint32_t a[2][4];
                #pragma unroll
                for (int mt = 0; mt < 2; ++mt) {
                    uint32_t off = panel * 16384
                        + SWZ((uint32_t)((m0w + mt * 16 + (lane & 15)) * 128
                                         + ks * 32 + (lane >> 4) * 16));
                    ldsm4(a[mt], sbase + off);
                }
                uint32_t b[8];
                #pragma unroll
                for (int p = 0; p < 2; ++p) {
                    uint32_t off = panel * 8192
                        + SWZ((uint32_t)((n0w + p * 16 + (lane & 7) + ((lane >> 4) & 1) * 8) * 128
                                         + ks * 32 + ((lane >> 3) & 1) * 16));
                    ldsm4(&b[p * 4], bbase + off);
                }
                #pragma unroll
                for (int mt = 0; mt < 2; ++mt)
                    #pragma unroll
                    for (int nt = 0; nt < 4; ++nt)
                        mma_tf32(C[mt][nt], a[mt], &b[(nt >> 1) * 4 + (nt & 1) * 2]);
            }
        }

        #pragma unroll
        for (int mt = 0; mt < 2; ++mt) {
            int tb = t0 + m0w + mt * 16 + (lane >> 2);
            #pragma unroll
            for (int nt = 0; nt < 4; ++nt) {
                int col = n0w + nt * 8 + (lane & 3) * 2;
                #pragma unroll
                for (int hf = 0; hf < 2; ++hf) {
                    int ts = (tb + hf * 8) & 1023;
                    float y0 = C[mt][nt][hf * 2 + 0];
                    float y1 = C[mt][nt][hf * 2 + 1];
                    if (m == 0) {
                        size_t o = ((size_t)ng * TT + ts) * 64 + col;
                        *(__half2*)(g_q + o) = __floats2half2_rn(y0, y1);
                    } else if (m == 1) {
                        size_t o = ((size_t)ng * KPAD + ts) * 64 + col;
                        *(__half2*)(g_k + o) = __floats2half2_rn(y0, y1);
                    } else {
                        g_vT[((size_t)ng * 64 + col)     * LPAD + ts] = __float2half(y0);
                        g_vT[((size_t)ng * 64 + col + 1) * LPAD + ts] = __float2half(y1);
                    }
                }
            }
        }
    }
}

// ---------------------- fp16 HMMA GEMM (outproj / conv) ---------------------
#define G_A 0
#define G_B 16384
#define G_BUF 32768
#define GEMM_SMEM (2 * G_BUF)

__global__ void __launch_bounds__(256, 2) gemm_hmma_kernel(
    int mode, int nchunk,
    const __half* __restrict__ IN,
    const __half* __restrict__ Bg,
    const float* __restrict__ bias,
    const float* __restrict__ residf,
    const __half* __restrict__ residh,
    const int* __restrict__ seq_mask,
    void* __restrict__ OUTv)
{
    extern __shared__ char smem[];
    const uint32_t sbase = smem_u32(smem);
    const int tid = threadIdx.x;
    const int lane = tid & 31, wid = tid >> 5;
    const int t0 = blockIdx.x * 128;
    const int co0 = blockIdx.y * 128;
    const int nBseq = t0 & ~1023;
    const int m0w = (wid & 1) * 64;
    const int n0w = (wid >> 1) * 32;

    float C[4][4][4];
    #pragma unroll
    for (int mt = 0; mt < 4; ++mt)
        #pragma unroll
        for (int nt = 0; nt < 4; ++nt)
            #pragma unroll
            for (int i = 0; i < 4; ++i) C[mt][nt][i] = 0.f;

    auto load_chunk = [&](int c, uint32_t bb) {
        int shift, cib;
        if (mode == 0) { shift = 0; cib = c << 6; }
        else           { shift = (c >> 3) - 2; cib = (c & 7) << 6; }
        #pragma unroll
        for (int it = 0; it < 4; ++it) {
            int s = it * 256 + tid;
            int r = s >> 3, cb = s & 7;
            int grow = t0 + r + shift;
            int ok = (grow >= nBseq);
            int ga = ok ? grow : nBseq;
            cpasync16z(bb + G_A + SWZ((uint32_t)(r * 128 + cb * 16)),
                       IN + (size_t)ga * 512 + cib + cb * 8, ok ? 16 : 0);
        }
        #pragma unroll
        for (int it = 0; it < 4; ++it) {
            int s = it * 256 + tid;
            int r = s >> 3, cb = s & 7;
            size_t gb = ((size_t)(c * 512 + co0 + r) << 6) + cb * 8;
            cpasync16(bb + G_B + SWZ((uint32_t)(r * 128 + cb * 16)), Bg + gb);
        }
        cp_commit();
    };

    load_chunk(0, sbase);

    for (int c = 0; c < nchunk; ++c) {
        const bool hn = (c + 1 < nchunk);
        if (hn) load_chunk(c + 1, sbase + ((c + 1) & 1) * G_BUF);
        if (hn) cp_wait1(); else cp_wait0();
        __syncthreads();

        const uint32_t Ab = sbase + (c & 1) * G_BUF;
        #pragma unroll
        for (int ks = 0; ks < 4; ++ks) {
            uint32_t a[4][4];
            #pragma unroll
            for (int mt = 0; mt < 4; ++mt) {
                uint32_t off = SWZ((uint32_t)((m0w + mt * 16 + (lane & 15)) * 128
                                              + ks * 32 + (lane >> 4) * 16));
                ldsm4(a[mt], Ab + G_A + off);
            }
            uint32_t b[8];
            #pragma unroll
            for (int p = 0; p < 2; ++p) {
                uint32_t off = SWZ((uint32_t)((n0w + p * 16 + (lane & 7) + ((lane >> 4) & 1) * 8) * 128
                                              + ks * 32 + ((lane >> 3) & 1) * 16));
                ldsm4(&b[p * 4], Ab + G_B + off);
            }
            #pragma unroll
            for (int mt = 0; mt < 4; ++mt)
                #pragma unroll
                for (int nt = 0; nt < 4; ++nt)
                    mma_f16(C[mt][nt], a[mt], &b[(nt >> 1) * 4 + (nt & 1) * 2]);
        }
        __syncthreads();
    }

    #pragma unroll
    for (int mt = 0; mt < 4; ++mt) {
        int rb = t0 + m0w + mt * 16 + (lane >> 2);
        #pragma unroll
        for (int nt = 0; nt < 4; ++nt) {
            int col = co0 + n0w + nt * 8 + (lane & 3) * 2;
            float b0 = bias[col], b1 = bias[col + 1];
            #pragma unroll
            for (int hf = 0; hf < 2; ++hf) {
                int r = rb + hf * 8;
                float y0 = C[mt][nt][hf * 2 + 0] + b0;
                float y1 = C[mt][nt][hf * 2 + 1] + b1;
                if (mode == 0) {
                    const float2 rs = *(const float2*)(residf + (size_t)r * 512 + col);
                    *(__half2*)((__half*)OUTv + (size_t)r * 512 + col) =
                        __floats2half2_rn(y0 + rs.x, y1 + rs.y);
                } else {
                    float valid = (float)seq_mask[r];
                    y0 = fmaxf(y0 * valid, 0.f);
                    y1 = fmaxf(y1 * valid, 0.f);
                    if (mode == 2) {
                        float2 rs = __half22float2(
                            *(const __half2*)(residh + (size_t)r * 512 + col));
                        y0 = fmaxf(y0 + rs.x, 0.f);
                        y1 = fmaxf(y1 + rs.y, 0.f);
                        *(float2*)((float*)OUTv + (size_t)r * 512 + col) =
                            make_float2(y0, y1);
                    } else {
                        *(__half2*)((__half*)OUTv + (size_t)r * 512 + col) =
                            __floats2half2_rn(y0, y1);
                    }
                }
            }
        }
    }
}

// ------- persistent kv slots (k + vT) + k padding + vT padding -------------
__global__ void persist_pad_kernel(const float* __restrict__ pk,
                                   const float* __restrict__ pv) {
    int idx = blockIdx.x * 256 + threadIdx.x;
    if (idx < NB * PP * HH * DD) {                      // 65536
        int d = idx & 63, h = (idx >> 6) & 7, p = (idx >> 9) & 15, n = idx >> 13;
        int src = ((p * HH + h) << 6) + d;
        int ng = n * 8 + h;
        g_vT[((size_t)ng * 64 + d) * LPAD + TT + p] = __float2half(pv[src]);
        g_k[((size_t)ng * KPAD + TT + p) * 64 + d] = __float2half(pk[src]);
        return;
    }
    int j = idx - NB * PP * HH * DD;
    if (j < 64 * 112 * 64) {                            // k pad rows [LP,KPAD)
        int d = j & 63;
        int l = LP + ((j >> 6) % 112);
        int ng = j / (112 * 64);
        g_k[((size_t)ng * KPAD + l) * 64 + d] = __float2half(0.f);
        return;
    }
    j -= 64 * 112 * 64;
    if (j < 64 * 64 * 48) {                             // vT pad cols [LP,LPAD)
        int c = j % 48;
        int d = (j / 48) & 63;
        int ng = j / (48 * 64);
        g_vT[((size_t)ng * 64 + d) * LPAD + LP + c] = __float2half(0.f);
    }
}

// -------------------- energy: raw Q@K^T -> fp16 (fp16 HMMA) ----------------
#define E_A0 0
#define E_B0 16384
#define EGY_SMEM 32768
__global__ void __launch_bounds__(256) energy_hmma_kernel() {
    extern __shared__ char smem[];
    const uint32_t sbase = smem_u32(smem);
    const int tid = threadIdx.x;
    const int lane = tid & 31, wid = tid >> 5;
    const int qt = blockIdx.x;          // 8
    const int kt = blockIdx.y;          // 9
    const int ng = blockIdx.z;          // 64
    const int m0w = (wid & 1) * 64;
    const int n0w = (wid >> 1) * 32;

    #pragma unroll
    for (int it = 0; it < 4; ++it) {
        int s = it * 256 + tid;
        int r = s >> 3, cb = s & 7;
        uint32_t off = SWZ((uint32_t)(r * 128 + cb * 16));
        size_t qa = ((size_t)ng * TT + qt * 128 + r) * 64 + cb * 8;
        size_t ka = ((size_t)ng * KPAD + kt * 128 + r) * 64 + cb * 8;
        cpasync16(sbase + E_A0 + off, g_q + qa);
        cpasync16(sbase + E_B0 + off, g_k + ka);
    }
    cp_commit();

    float C[4][4][4];
    #pragma unroll
    for (int mt = 0; mt < 4; ++mt)
        #pragma unroll
        for (int nt = 0; nt < 4; ++nt)
            #pragma unroll
            for (int i = 0; i < 4; ++i) C[mt][nt][i] = 0.f;

    cp_wait0();
    __syncthreads();

    #pragma unroll
    for (int ks = 0; ks < 4; ++ks) {
        uint32_t a[4][4];
        #pragma unroll
        for (int mt = 0; mt < 4; ++mt) {
            uint32_t off = SWZ((uint32_t)((m0w + mt * 16 + (lane & 15)) * 128
                                          + ks * 32 + (lane >> 4) * 16));
            ldsm4(a[mt], sbase + E_A0 + off);
        }
        uint32_t b[8];
        #pragma unroll
        for (int p = 0; p < 2; ++p) {
            uint32_t off = SWZ((uint32_t)((n0w + p * 16 + (lane & 7) + ((lane >> 4) & 1) * 8) * 128
                                          + ks * 32 + ((lane >> 3) & 1) * 16));
            ldsm4(&b[p * 4], sbase + E_B0 + off);
        }
        #pragma unroll
        for (int mt = 0; mt < 4; ++mt)
            #pragma unroll
            for (int nt = 0; nt < 4; ++nt)
                mma_f16(C[mt][nt], a[mt], &b[(nt >> 1) * 4 + (nt & 1) * 2]);
    }

    #pragma unroll
    for (int mt = 0; mt < 4; ++mt) {
        int qb = qt * 128 + m0w + mt * 16 + (lane >> 2);
        #pragma unroll
        for (int nt = 0; nt < 4; ++nt) {
            int k0 = kt * 128 + n0w + nt * 8 + (lane & 3) * 2;
            if (k0 >= LP) continue;
            #pragma unroll
            for (int hf = 0; hf < 2; ++hf) {
                int q = qb + hf * 8;
                __half2 e = __floats2half2_rn(C[mt][nt][hf * 2 + 0],
                                              C[mt][nt][hf * 2 + 1]);
                *(__half2*)(g_att + ((size_t)(ng * TT + q)) * LP + k0) = e;
            }
        }
    }
}

// -- pre-mix(+ALiBi) -> exp (max-free, transient) -> sum -> post-mix --------
__global__ void __launch_bounds__(256, 4) softmax_kernel(
                               const float* __restrict__ pre,
                               const float* __restrict__ post,
                               const int* __restrict__ seq_mask) {
    __shared__ float sm[8][LP];
    __shared__ float ps_pre[64];
    __shared__ float ps_post[64];
    __shared__ float inv_s[8];
    const int nq = blockIdx.x;
    const int n = nq >> 10, q = nq & 1023;
    const int tid = threadIdx.x;

    if (tid < 64) {
        ps_pre[tid] = pre[tid] * SOFTMAX_SCALE;     // fold scale into premix
        ps_post[tid] = post[tid];
    }

    for (int i8 = tid; i8 < 8 * (LP / 8); i8 += 256) {
        int h = i8 / (LP / 8), kk8 = (i8 - h * (LP / 8)) * 8;
        const __half2* src = (const __half2*)(g_att + ((size_t)((n * 8 + h) * TT + q)) * LP + kk8);
        #pragma unroll
        for (int u = 0; u < 4; ++u) {
            float2 f = __half22float2(src[u]);
            sm[h][kk8 + u * 2 + 0] = f.x;
            sm[h][kk8 + u * 2 + 1] = f.y;
        }
    }
    __syncthreads();

    // premixed+scaled ALiBi slopes
    float spre[8];
    #pragma unroll
    for (int g = 0; g < 8; g++) {
        float s = 0.f;
        #pragma unroll
        for (int h = 0; h < 8; h++) s += ps_pre[g * 8 + h] * exp2f(-(float)(h + 1));
        spre[g] = s;
    }

    // premix + ALiBi + mask + exp -> smem (logits bounded, no max needed;
    // no loop-carried accumulators -> same register pressure as R13 pass)
    const float fq = (float)q;
    for (int kk0 = tid * 4; kk0 < LP; kk0 += 1024) {
        float4 a[8];
        #pragma unroll
        for (int h = 0; h < 8; h++) a[h] = *(const float4*)&sm[h][kk0];
        int4 msk = make_int4(1, 1, 1, 1);
        float4 dist = make_float4(0.f, 0.f, 0.f, 0.f);
        if (kk0 < TT) {
            msk = *(const int4*)(seq_mask + n * TT + kk0);
            dist.x = fabsf(fq - (float)(kk0 + 0));
            dist.y = fabsf(fq - (float)(kk0 + 1));
            dist.z = fabsf(fq - (float)(kk0 + 2));
            dist.w = fabsf(fq - (float)(kk0 + 3));
        }
        #pragma unroll
        for (int g = 0; g < 8; g++) {
            float4 o = make_float4(0.f, 0.f, 0.f, 0.f);
            #pragma unroll
            for (int h = 0; h < 8; h++) {
                float w = ps_pre[g * 8 + h];
                o.x += w * a[h].x; o.y += w * a[h].y;
                o.z += w * a[h].z; o.w += w * a[h].w;
            }
            float sg = spre[g];
            o.x = msk.x ? __expf(o.x - dist.x * sg) : 0.f;
            o.y = msk.y ? __expf(o.y - dist.y * sg) : 0.f;
            o.z = msk.z ? __expf(o.z - dist.z * sg) : 0.f;
            o.w = msk.w ? __expf(o.w - dist.w * sg) : 0.f;
            *(float4*)&sm[g][kk0] = o;
        }
    }
    __syncthreads();

    // warp w: sum-only scan of row w (float4-vectorized; no max, no writeback)
    const int w = tid >> 5, lane = tid & 31;
    float s = 0.f;
    for (int kk = lane * 4; kk < LP; kk += 128) {
        float4 v = *(const float4*)&sm[w][kk];
        s += v.x + v.y + v.z + v.w;
    }
    #pragma unroll
    for (int o = 16; o; o >>= 1) s += __shfl_xor_sync(0xffffffffu, s, o);
    if (lane == 0) inv_s[w] = 1.f / s;
    __syncthreads();

    float inv[8];
    #pragma unroll
    for (int h = 0; h < 8; h++) inv[h] = inv_s[h];
    for (int kk0 = tid * 4; kk0 < LPAD; kk0 += 1024) {
        float4 a[8];
        if (kk0 < LP) {
            #pragma unroll
            for (int h = 0; h < 8; h++) {
                a[h] = *(const float4*)&sm[h][kk0];
                a[h].x *= inv[h]; a[h].y *= inv[h];
                a[h].z *= inv[h]; a[h].w *= inv[h];
            }
        } else {
            #pragma unroll
            for (int h = 0; h < 8; h++) a[h] = make_float4(0.f, 0.f, 0.f, 0.f);
        }
        #pragma unroll
        for (int g = 0; g < 8; g++) {
            float4 o = make_float4(0.f, 0.f, 0.f, 0.f);
            #pragma unroll
            for (int h = 0; h < 8; h++) {
                float wgt = ps_post[g * 8 + h];
                o.x += wgt * a[h].x; o.y += wgt * a[h].y;
                o.z += wgt * a[h].z; o.w += wgt * a[h].w;
            }
            __half2 h01 = __floats2half2_rn(o.x, o.y);
            __half2 h23 = __floats2half2_rn(o.z, o.w);
            __half2* dst = (__half2*)(g_a + ((size_t)((n * 8 + g) * TT + q)) * LPAD + kk0);
            dst[0] = h01;
            dst[1] = h23;
        }
    }
}

// ------------------------- attn @ V (fp16 HMMA) -----------------------------
#define V_A 0
#define V_B 16384
#define V_BUF 24576
#define AV_SMEM (2 * V_BUF)

__global__ void __launch_bounds__(256, 2) av_hmma_kernel() {
    extern __shared__ char smem[];
    const uint32_t sbase = smem_u32(smem);
    const int tid = threadIdx.x;
    const int lane = tid & 31, wid = tid >> 5;
    const int qt = blockIdx.x;          // 8
    const int ng = blockIdx.y;          // 64
    const int m0w = (wid & 3) * 32;
    const int n0w = (wid >> 2) * 32;

    float C[2][4][4];
    #pragma unroll
    for (int mt = 0; mt < 2; ++mt)
        #pragma unroll
        for (int nt = 0; nt < 4; ++nt)
            #pragma unroll
            for (int i = 0; i < 4; ++i) C[mt][nt][i] = 0.f;

    auto load_chunk = [&](int c, uint32_t bb) {
        #pragma unroll
        for (int it = 0; it < 4; ++it) {
            int s = it * 256 + tid;
            int r = s >> 3, cb = s & 7;
            size_t ga = ((size_t)ng * TT + qt * 128 + r) * LPAD + c * 64 + cb * 8;
            cpasync16(bb + V_A + SWZ((uint32_t)(r * 128 + cb * 16)), g_a + ga);
        }
        #pragma unroll
        for (int it = 0; it < 2; ++it) {
            int s = it * 256 + tid;
            int r = s >> 3, cb = s & 7;
            size_t gb = ((size_t)ng * 64 + r) * LPAD + c * 64 + cb * 8;
            cpasync16(bb + V_B + SWZ((uint32_t)(r * 128 + cb * 16)), g_vT + gb);
        }
        cp_commit();
    };

    load_chunk(0, sbase);

    for (int c = 0; c < 17; ++c) {
        const bool hn = (c + 1 < 17);
        if (hn) load_chunk(c + 1, sbase + ((c + 1) & 1) * V_BUF);
        if (hn) cp_wait1(); else cp_wait0();
        __syncthreads();

        const uint32_t Ab = sbase + (c & 1) * V_BUF;
        #pragma unroll
        for (int ks = 0; ks < 4; ++ks) {
            uint32_t a[2][4];
            #pragma unroll
            for (int mt = 0; mt < 2; ++mt) {
                uint32_t off = SWZ((uint32_t)((m0w + mt * 16 + (lane & 15)) * 128
                                              + ks * 32 + (lane >> 4) * 16));
                ldsm4(a[mt], Ab + V_A + off);
            }
            uint32_t b[8];
            #pragma unroll
            for (int p = 0; p < 2; ++p) {
                uint32_t off = SWZ((uint32_t)((n0w + p * 16 + (lane & 7) + ((lane >> 4) & 1) * 8) * 128
                                              + ks * 32 + ((lane >> 3) & 1) * 16));
                ldsm4(&b[p * 4], Ab + V_B + off);
            }
            #pragma unroll
            for (int mt = 0; mt < 2; ++mt)
                #pragma unroll
                for (int nt = 0; nt < 4; ++nt)
                    mma_f16(C[mt][nt], a[mt], &b[(nt >> 1) * 4 + (nt & 1) * 2]);
        }
        __syncthreads();
    }

    const int n = ng >> 3, h = ng & 7;
    #pragma unroll
    for (int mt = 0; mt < 2; ++mt) {
        int qb = qt * 128 + m0w + mt * 16 + (lane >> 2);
        #pragma unroll
        for (int nt = 0; nt < 4; ++nt) {
            int dcol = n0w + nt * 8 + (lane & 3) * 2;
            #pragma unroll
            for (int hf = 0; hf < 2; ++hf) {
                int q = qb + hf * 8;
                size_t o = ((size_t)(n * TT + q)) * 512 + h * 64 + dcol;
                *(__half2*)(g_ctx + o) =
                    __floats2half2_rn(C[mt][nt][hf * 2 + 0], C[mt][nt][hf * 2 + 1]);
            }
        }
    }
}

// ------------------------- LayerNorm (warp per row) -------------------------
__global__ void __launch_bounds__(256) ln_kernel(
                          const float* __restrict__ gamma,
                          const float* __restrict__ beta,
                          float* __restrict__ out) {
    const int lane = threadIdx.x & 31, wid = threadIdx.x >> 5;
    const int r = blockIdx.x * 8 + wid;
    const float* in = g_t2 + (size_t)r * EE;

    float4 v[4];
    float s = 0.f;
    #pragma unroll
    for (int i = 0; i < 4; ++i) {
        v[i] = *(const float4*)(in + i * 128 + lane * 4);
        s += v[i].x + v[i].y + v[i].z + v[i].w;
    }
    #pragma unroll
    for (int o = 16; o; o >>= 1) s += __shfl_xor_sync(0xffffffffu, s, o);
    float mu = s * (1.f / EE);

    float vs = 0.f;
    #pragma unroll
    for (int i = 0; i < 4; ++i) {
        float dx = v[i].x - mu, dy = v[i].y - mu, dz = v[i].z - mu, dw = v[i].w - mu;
        vs += dx * dx + dy * dy + dz * dz + dw * dw;
    }
    #pragma unroll
    for (int o = 16; o; o >>= 1) vs += __shfl_xor_sync(0xffffffffu, vs, o);
    float inv = rsqrtf(vs * (1.f / EE) + 1e-5f);

    #pragma unroll
    for (int i = 0; i < 4; ++i) {
        int col = i * 128 + lane * 4;
        float4 g = *(const float4*)(gamma + col);
        float4 b = *(const float4*)(beta + col);
        float4 o;
        o.x = (v[i].x - mu) * inv * g.x + b.x;
        o.y = (v[i].y - mu) * inv * g.y + b.y;
        o.z = (v[i].z - mu) * inv * g.z + b.z;
        o.w = (v[i].w - mu) * inv * g.w + b.w;
        *(float4*)(out + (size_t)r * EE + col) = o;
    }
}

// ------------------------------ launcher -----------------------------------
extern "C" void kernel_launch(void* const* d_in, const int* in_sizes, int n_in,
                              void* d_out, int out_size) {
    const float* x        = (const float*)d_in[0];
    const int*   seq_mask = (const int*)  d_in[1];
    const float* Wq       = (const float*)d_in[2];
    const float* Wk       = (const float*)d_in[3];
    const float* Wv       = (const float*)d_in[4];
    const float* Wo       = (const float*)d_in[5];
    const float* bo       = (const float*)d_in[6];
    const float* pre_th   = (const float*)d_in[7];
    const float* post_th  = (const float*)d_in[8];
    const float* pk       = (const float*)d_in[9];
    const float* pv       = (const float*)d_in[10];
    const float* c1W      = (const float*)d_in[11];
    const float* c1b      = (const float*)d_in[12];
    const float* c2W      = (const float*)d_in[13];
    const float* c2b      = (const float*)d_in[14];
    const float* ln_g     = (const float*)d_in[15];
    const float* ln_b     = (const float*)d_in[16];
    float* out = (float*)d_out;

    __half *pWo, *pC1, *pC2, *pCtx, *pH, *pT1;
    float *pT2;
    cudaGetSymbolAddress((void**)&pWo,  g_Wo);
    cudaGetSymbolAddress((void**)&pC1,  g_c1);
    cudaGetSymbolAddress((void**)&pC2,  g_c2);
    cudaGetSymbolAddress((void**)&pCtx, g_ctx);
    cudaGetSymbolAddress((void**)&pH,   g_h);
    cudaGetSymbolAddress((void**)&pT1,  g_t1);
    cudaGetSymbolAddress((void**)&pT2,  g_t2);

    cudaFuncSetAttribute(gemm_hmma_kernel,
                         cudaFuncAttributeMaxDynamicSharedMemorySize, GEMM_SMEM);
    cudaFuncSetAttribute(energy_hmma_kernel,
                         cudaFuncAttributeMaxDynamicSharedMemorySize, EGY_SMEM);
    cudaFuncSetAttribute(av_hmma_kernel,
                         cudaFuncAttributeMaxDynamicSharedMemorySize, AV_SMEM);
    cudaFuncSetAttribute(qkv_hmma_kernel,
                         cudaFuncAttributeMaxDynamicSharedMemorySize, QKV_SMEM);

    wo_convert<<<1024, 256>>>(Wo, pWo);
    conv_w_convert<<<3072, 256>>>(c1W, pC1);
    conv_w_convert<<<3072, 256>>>(c2W, pC2);

    qkv_hmma_kernel<<<dim3(64, 8), 256, QKV_SMEM>>>(x, Wq, Wk, Wv);
    persist_pad_kernel<<<2816, 256>>>(pk, pv);

    energy_hmma_kernel<<<dim3(8, 9, 64), 256, EGY_SMEM>>>();
    softmax_kernel<<<8192, 256>>>(pre_th, post_th, seq_mask);
    av_hmma_kernel<<<dim3(8, 64), 256, AV_SMEM>>>();

    gemm_hmma_kernel<<<dim3(64, 4), 256, GEMM_SMEM>>>(
        0, 8, pCtx, pWo, bo, x, nullptr, seq_mask, pH);
    gemm_hmma_kernel<<<dim3(64, 4), 256, GEMM_SMEM>>>(
        1, 24, pH, pC1, c1b, nullptr, nullptr, seq_mask, pT1);
    gemm_hmma_kernel<<<dim3(64, 4), 256, GEMM_SMEM>>>(
        2, 24, pT1, pC2, c2b, nullptr, pH, seq_mask, pT2);

    ln_kernel<<<1024, 256>>>(ln_g, ln_b, out);
}

// round 15
// speedup vs baseline: 1.5800x; 1.5800x over previous
#include <cuda_runtime.h>
#include <cuda_bf16.h>
#include <cuda_fp16.h>
#include <math.h>
#include <stdint.h>

// ---------------------------------------------------------------------------
// TCNAttentionBlock. R15: R13 base (verified 413us) + float4-vectorized
// max/exp warp pass in softmax (exp stays OUT of the premix loop - the
// R12/R14 regressions both came from exp-in-premix).
// N=8, T=1024, E=512, H=8, D=64, P=16.
// ---------------------------------------------------------------------------

#define NB   8
#define TT   1024
#define EE   512
#define HH   8
#define DD   64
#define PP   16
#define LP   1040            // TT + PP
#define LPAD 1088            // attn row padded (17 chunks of 64)
#define KPAD 1152            // K rows padded (9 tiles of 128)
#define SOFTMAX_SCALE 0.044194173824159216f   // 1/sqrt(512)

// ------------------------------ scratch -----------------------------------
__device__ __half g_q  [64 * TT * DD];                     // fp16 [ng][q][64]
__device__ __half g_k  [64 * KPAD * DD];                   // fp16 [ng][l][64]
__device__ __half g_vT [64 * DD * LPAD];                   // fp16 [ng][d][1088]
__device__ __half g_att[(size_t)64 * TT * LP];             // fp16 raw QK^T
__device__ __half g_a  [(size_t)64 * TT * LPAD];           // fp16 attn
__device__ __half g_ctx[NB * TT * EE];                     // fp16
__device__ __half g_h  [NB * TT * EE];                     // fp16 (x + att)
__device__ __half g_t1 [NB * TT * EE];                     // fp16
__device__ float  g_t2 [NB * TT * EE];                     // fp32

// preconverted fp16 weights, layout [chunk][co(512)][64]
__device__ __half g_Wo[8  * 512 * 64];
__device__ __half g_c1[24 * 512 * 64];
__device__ __half g_c2[24 * 512 * 64];

// ---------------------------- PTX helpers ----------------------------------
__device__ __forceinline__ uint32_t smem_u32(const void* p) {
    uint32_t a;
    asm("{ .reg .u64 t; cvta.to.shared.u64 t, %1; cvt.u32.u64 %0, t; }"
        : "=r"(a) : "l"(p));
    return a;
}
#define SWZ(o) ((o) ^ (((o) >> 3) & 0x70))

__device__ __forceinline__ void ldsm4(uint32_t* r, uint32_t addr) {
    asm volatile("ldmatrix.sync.aligned.m8n8.x4.shared.b16 {%0,%1,%2,%3}, [%4];"
                 : "=r"(r[0]), "=r"(r[1]), "=r"(r[2]), "=r"(r[3]) : "r"(addr));
}
__device__ __forceinline__ void mma_f16(float* c, const uint32_t* a, const uint32_t* b) {
    asm volatile(
        "mma.sync.aligned.m16n8k16.row.col.f32.f16.f16.f32 "
        "{%0,%1,%2,%3}, {%4,%5,%6,%7}, {%8,%9}, {%0,%1,%2,%3};"
        : "+f"(c[0]), "+f"(c[1]), "+f"(c[2]), "+f"(c[3])
        : "r"(a[0]), "r"(a[1]), "r"(a[2]), "r"(a[3]), "r"(b[0]), "r"(b[1]));
}
__device__ __forceinline__ void cpasync16(uint32_t saddr, const void* g) {
    asm volatile("cp.async.cg.shared.global [%0], [%1], 16;" :: "r"(saddr), "l"(g));
}
__device__ __forceinline__ void cpasync16z(uint32_t saddr, const void* g, int sz) {
    asm volatile("cp.async.cg.shared.global [%0], [%1], 16, %2;"
                 :: "r"(saddr), "l"(g), "r"(sz));
}
__device__ __forceinline__ void cp_commit() {
    asm volatile("cp.async.commit_group;" ::: "memory");
}
__device__ __forceinline__ void cp_wait0() {
    asm volatile("cp.async.wait_group 0;" ::: "memory");
}
__device__ __forceinline__ void cp_wait1() {
    asm volatile("cp.async.wait_group 1;" ::: "memory");
}
__device__ __forceinline__ uint32_t tf32r_u(float v) {   // for A staging in qkv
    uint32_t u;
    asm("cvt.rna.tf32.f32 %0, %1;" : "=r"(u) : "f"(v));
    return u;
}
__device__ __forceinline__ void mma_tf32(float* c, const uint32_t* a, const uint32_t* b) {
    asm volatile(
        "mma.sync.aligned.m16n8k8.row.col.f32.tf32.tf32.f32 "
        "{%0,%1,%2,%3}, {%4,%5,%6,%7}, {%8,%9}, {%0,%1,%2,%3};"
        : "+f"(c[0]), "+f"(c[1]), "+f"(c[2]), "+f"(c[3])
        : "r"(a[0]), "r"(a[1]), "r"(a[2]), "r"(a[3]), "r"(b[0]), "r"(b[1]));
}

// ---------------------- weight preconversion (fp16) -------------------------
__global__ void conv_w_convert(const float* __restrict__ W, __half* __restrict__ o) {
    int d = blockIdx.x * 256 + threadIdx.x;          // 24*512*64 = 786432
    int c  = d >> 15;
    int co = (d >> 6) & 511;
    int ci = d & 63;
    int tap = c >> 3, cib = (c & 7) << 6;
    o[d] = __float2half(W[(size_t)(co * 512 + cib + ci) * 3 + tap]);
}
__global__ void wo_convert(const float* __restrict__ W, __half* __restrict__ o) {
    int d = blockIdx.x * 256 + threadIdx.x;          // 8*512*64 = 262144
    int c  = d >> 15;
    int co = (d >> 6) & 511;
    int ci = d & 63;
    o[d] = __float2half(W[co * 512 + (c << 6) + ci]);
}

// ------------------------ QKV on tf32 HMMA ----------------------------------
#define QKV_B0 32768
#define QKV_SMEM (32768 + 3 * 16384)
__global__ void __launch_bounds__(256, 2) qkv_hmma_kernel(
    const float* __restrict__ x,
    const float* __restrict__ Wq,
    const float* __restrict__ Wk,
    const float* __restrict__ Wv)
{
    extern __shared__ char smem[];
    const uint32_t sbase = smem_u32(smem);
    const int tid = threadIdx.x;
    const int lane = tid & 31, wid = tid >> 5;
    const int t0 = blockIdx.x * 128;
    const int h  = blockIdx.y;
    const int n  = t0 >> 10;
    const int ng = n * 8 + h;
    const int m0w = (wid & 3) * 32;
    const int n0w = (wid >> 2) * 32;

    #pragma unroll
    for (int it = 0; it < 8; ++it) {
        int lin = it * 1024 + tid * 4;
        int r = lin >> 6, ci = lin & 63;
        float4 v = *(const float4*)(x + (size_t)(t0 + r) * 512 + h * 64 + ci);
        uint32_t off = (ci >> 5) * 16384 + SWZ((uint32_t)(r * 128 + (ci & 31) * 4));
        *(uint4*)(smem + off) = make_uint4(tf32r_u(v.x), tf32r_u(v.y),
                                           tf32r_u(v.z), tf32r_u(v.w));
    }
    #pragma unroll
    for (int m = 0; m < 3; ++m) {
        const float* Wm = (m == 0) ? Wq : (m == 1) ? Wk : Wv;
        #pragma unroll
        for (int it = 0; it < 4; ++it) {
            int lin = it * 1024 + tid * 4;
            int r = lin >> 6, ci = lin & 63;
            float4 v = *(const float4*)(Wm + r * 64 + ci);
            uint32_t off = QKV_B0 + m * 16384 + (ci >> 5) * 8192
                         + SWZ((uint32_t)(r * 128 + (ci & 31) * 4));
            *(uint4*)(smem + off) = make_uint4(tf32r_u(v.x), tf32r_u(v.y),
                                               tf32r_u(v.z), tf32r_u(v.w));
        }
    }
    __syncthreads();

    for (int m = 0; m < 3; ++m) {
        float C[2][4][4];
        #pragma unroll
        for (int mt = 0; mt < 2; ++mt)
            #pragma unroll
            for (int nt = 0; nt < 4; ++nt)
                #pragma unroll
                for (int i = 0; i < 4; ++i) C[mt][nt][i] = 0.f;

        const uint32_t bbase = sbase + QKV_B0 + m * 16384;
        #pragma unroll
        for (int panel = 0; panel < 2; ++panel) {
            #pragma unroll
            for (int ks = 0; ks < 4; ++ks) {
                uint32_t a[2][4];
                #pragma unroll
                for (int mt = 0; mt < 2; ++mt) {
                    uint32_t off = panel * 16384
                        + SWZ((uint32_t)((m0w + mt * 16 + (lane & 15)) * 128
                                         + ks * 32 + (lane >> 4) * 16));
                    ldsm4(a[mt], sbase + off);
                }
                uint32_t b[8];
                #pragma unroll
                for (int p = 0; p < 2; ++p) {
                    uint32_t off = panel * 8192
                        + SWZ((uint32_t)((n0w + p * 16 + (lane & 7) + ((lane >> 4) & 1) * 8) * 128
                                         + ks * 32 + ((lane >> 3) & 1) * 16));
                    ldsm4(&b[p * 4], bbase + off);
                }
                #pragma unroll
                for (int mt = 0; mt < 2; ++mt)
                    #pragma unroll
                    for (int nt = 0; nt < 4; ++nt)
                        mma_tf32(C[mt][nt], a[mt], &b[(nt >> 1) * 4 + (nt & 1) * 2]);
            }
        }

        #pragma unroll
        for (int mt = 0; mt < 2; ++mt) {
            int tb = t0 + m0w + mt * 16 + (lane >> 2);
            #pragma unroll
            for (int nt = 0; nt < 4; ++nt) {
                int col = n0w + nt * 8 + (lane & 3) * 2;
                #pragma unroll
                for (int hf = 0; hf < 2; ++hf) {
                    int ts = (tb + hf * 8) & 1023;
                    float y0 = C[mt][nt][hf * 2 + 0];
                    float y1 = C[mt][nt][hf * 2 + 1];
                    if (m == 0) {
                        size_t o = ((size_t)ng * TT + ts) * 64 + col;
                        *(__half2*)(g_q + o) = __floats2half2_rn(y0, y1);
                    } else if (m == 1) {
                        size_t o = ((size_t)ng * KPAD + ts) * 64 + col;
                        *(__half2*)(g_k + o) = __floats2half2_rn(y0, y1);
                    } else {
                        g_vT[((size_t)ng * 64 + col)     * LPAD + ts] = __float2half(y0);
                        g_vT[((size_t)ng * 64 + col + 1) * LPAD + ts] = __float2half(y1);
                    }
                }
            }
        }
    }
}

// ---------------------- fp16 HMMA GEMM (outproj / conv) ---------------------
#define G_A 0
#define G_B 16384
#define G_BUF 32768
#define GEMM_SMEM (2 * G_BUF)

__global__ void __launch_bounds__(256, 2) gemm_hmma_kernel(
    int mode, int nchunk,
    const __half* __restrict__ IN,
    const __half* __restrict__ Bg,
    const float* __restrict__ bias,
    const float* __restrict__ residf,
    const __half* __restrict__ residh,
    const int* __restrict__ seq_mask,
    void* __restrict__ OUTv)
{
    extern __shared__ char smem[];
    const uint32_t sbase = smem_u32(smem);
    const int tid = threadIdx.x;
    const int lane = tid & 31, wid = tid >> 5;
    const int t0 = blockIdx.x * 128;
    const int co0 = blockIdx.y * 128;
    const int nBseq = t0 & ~1023;
    const int m0w = (wid & 1) * 64;
    const int n0w = (wid >> 1) * 32;

    float C[4][4][4];
    #pragma unroll
    for (int mt = 0; mt < 4; ++mt)
        #pragma unroll
        for (int nt = 0; nt < 4; ++nt)
            #pragma unroll
            for (int i = 0; i < 4; ++i) C[mt][nt][i] = 0.f;

    auto load_chunk = [&](int c, uint32_t bb) {
        int shift, cib;
        if (mode == 0) { shift = 0; cib = c << 6; }
        else           { shift = (c >> 3) - 2; cib = (c & 7) << 6; }
        #pragma unroll
        for (int it = 0; it < 4; ++it) {
            int s = it * 256 + tid;
            int r = s >> 3, cb = s & 7;
            int grow = t0 + r + shift;
            int ok = (grow >= nBseq);
            int ga = ok ? grow : nBseq;
            cpasync16z(bb + G_A + SWZ((uint32_t)(r * 128 + cb * 16)),
                       IN + (size_t)ga * 512 + cib + cb * 8, ok ? 16 : 0);
        }
        #pragma unroll
        for (int it = 0; it < 4; ++it) {
            int s = it * 256 + tid;
            int r = s >> 3, cb = s & 7;
            size_t gb = ((size_t)(c * 512 + co0 + r) << 6) + cb * 8;
            cpasync16(bb + G_B + SWZ((uint32_t)(r * 128 + cb * 16)), Bg + gb);
        }
        cp_commit();
    };

    load_chunk(0, sbase);

    for (int c = 0; c < nchunk; ++c) {
        const bool hn = (c + 1 < nchunk);
        if (hn) load_chunk(c + 1, sbase + ((c + 1) & 1) * G_BUF);
        if (hn) cp_wait1(); else cp_wait0();
        __syncthreads();

        const uint32_t Ab = sbase + (c & 1) * G_BUF;
        #pragma unroll
        for (int ks = 0; ks < 4; ++ks) {
            uint32_t a[4][4];
            #pragma unroll
            for (int mt = 0; mt < 4; ++mt) {
                uint32_t off = SWZ((uint32_t)((m0w + mt * 16 + (lane & 15)) * 128
                                              + ks * 32 + (lane >> 4) * 16));
                ldsm4(a[mt], Ab + G_A + off);
            }
            uint32_t b[8];
            #pragma unroll
            for (int p = 0; p < 2; ++p) {
                uint32_t off = SWZ((uint32_t)((n0w + p * 16 + (lane & 7) + ((lane >> 4) & 1) * 8) * 128
                                              + ks * 32 + ((lane >> 3) & 1) * 16));
                ldsm4(&b[p * 4], Ab + G_B + off);
            }
            #pragma unroll
            for (int mt = 0; mt < 4; ++mt)
                #pragma unroll
                for (int nt = 0; nt < 4; ++nt)
                    mma_f16(C[mt][nt], a[mt], &b[(nt >> 1) * 4 + (nt & 1) * 2]);
        }
        __syncthreads();
    }

    #pragma unroll
    for (int mt = 0; mt < 4; ++mt) {
        int rb = t0 + m0w + mt * 16 + (lane >> 2);
        #pragma unroll
        for (int nt = 0; nt < 4; ++nt) {
            int col = co0 + n0w + nt * 8 + (lane & 3) * 2;
            float b0 = bias[col], b1 = bias[col + 1];
            #pragma unroll
            for (int hf = 0; hf < 2; ++hf) {
                int r = rb + hf * 8;
                float y0 = C[mt][nt][hf * 2 + 0] + b0;
                float y1 = C[mt][nt][hf * 2 + 1] + b1;
                if (mode == 0) {
                    const float2 rs = *(const float2*)(residf + (size_t)r * 512 + col);
                    *(__half2*)((__half*)OUTv + (size_t)r * 512 + col) =
                        __floats2half2_rn(y0 + rs.x, y1 + rs.y);
                } else {
                    float valid = (float)seq_mask[r];
                    y0 = fmaxf(y0 * valid, 0.f);
                    y1 = fmaxf(y1 * valid, 0.f);
                    if (mode == 2) {
                        float2 rs = __half22float2(
                            *(const __half2*)(residh + (size_t)r * 512 + col));
                        y0 = fmaxf(y0 + rs.x, 0.f);
                        y1 = fmaxf(y1 + rs.y, 0.f);
                        *(float2*)((float*)OUTv + (size_t)r * 512 + col) =
                            make_float2(y0, y1);
                    } else {
                        *(__half2*)((__half*)OUTv + (size_t)r * 512 + col) =
                            __floats2half2_rn(y0, y1);
                    }
                }
            }
        }
    }
}

// ------- persistent kv slots (k + vT) + k padding + vT padding -------------
__global__ void persist_pad_kernel(const float* __restrict__ pk,
                                   const float* __restrict__ pv) {
    int idx = blockIdx.x * 256 + threadIdx.x;
    if (idx < NB * PP * HH * DD) {                      // 65536
        int d = idx & 63, h = (idx >> 6) & 7, p = (idx >> 9) & 15, n = idx >> 13;
        int src = ((p * HH + h) << 6) + d;
        int ng = n * 8 + h;
        g_vT[((size_t)ng * 64 + d) * LPAD + TT + p] = __float2half(pv[src]);
        g_k[((size_t)ng * KPAD + TT + p) * 64 + d] = __float2half(pk[src]);
        return;
    }
    int j = idx - NB * PP * HH * DD;
    if (j < 64 * 112 * 64) {                            // k pad rows [LP,KPAD)
        int d = j & 63;
        int l = LP + ((j >> 6) % 112);
        int ng = j / (112 * 64);
        g_k[((size_t)ng * KPAD + l) * 64 + d] = __float2half(0.f);
        return;
    }
    j -= 64 * 112 * 64;
    if (j < 64 * 64 * 48) {                             // vT pad cols [LP,LPAD)
        int c = j % 48;
        int d = (j / 48) & 63;
        int ng = j / (48 * 64);
        g_vT[((size_t)ng * 64 + d) * LPAD + LP + c] = __float2half(0.f);
    }
}

// -------------------- energy: raw Q@K^T -> fp16 (fp16 HMMA) ----------------
#define E_A0 0
#define E_B0 16384
#define EGY_SMEM 32768
__global__ void __launch_bounds__(256) energy_hmma_kernel() {
    extern __shared__ char smem[];
    const uint32_t sbase = smem_u32(smem);
    const int tid = threadIdx.x;
    const int lane = tid & 31, wid = tid >> 5;
    const int qt = blockIdx.x;          // 8
    const int kt = blockIdx.y;          // 9
    const int ng = blockIdx.z;          // 64
    const int m0w = (wid & 1) * 64;
    const int n0w = (wid >> 1) * 32;

    #pragma unroll
    for (int it = 0; it < 4; ++it) {
        int s = it * 256 + tid;
        int r = s >> 3, cb = s & 7;
        uint32_t off = SWZ((uint32_t)(r * 128 + cb * 16));
        size_t qa = ((size_t)ng * TT + qt * 128 + r) * 64 + cb * 8;
        size_t ka = ((size_t)ng * KPAD + kt * 128 + r) * 64 + cb * 8;
        cpasync16(sbase + E_A0 + off, g_q + qa);
        cpasync16(sbase + E_B0 + off, g_k + ka);
    }
    cp_commit();

    float C[4][4][4];
    #pragma unroll
    for (int mt = 0; mt < 4; ++mt)
        #pragma unroll
        for (int nt = 0; nt < 4; ++nt)
            #pragma unroll
            for (int i = 0; i < 4; ++i) C[mt][nt][i] = 0.f;

    cp_wait0();
    __syncthreads();

    #pragma unroll
    for (int ks = 0; ks < 4; ++ks) {
        uint32_t a[4][4];
        #pragma unroll
        for (int mt = 0; mt < 4; ++mt) {
            uint32_t off = SWZ((uint32_t)((m0w + mt * 16 + (lane & 15)) * 128
                                          + ks * 32 + (lane >> 4) * 16));
            ldsm4(a[mt], sbase + E_A0 + off);
        }
        uint32_t b[8];
        #pragma unroll
        for (int p = 0; p < 2; ++p) {
            uint32_t off = SWZ((uint32_t)((n0w + p * 16 + (lane & 7) + ((lane >> 4) & 1) * 8) * 128
                                          + ks * 32 + ((lane >> 3) & 1) * 16));
            ldsm4(&b[p * 4], sbase + E_B0 + off);
        }
        #pragma unroll
        for (int mt = 0; mt < 4; ++mt)
            #pragma unroll
            for (int nt = 0; nt < 4; ++nt)
                mma_f16(C[mt][nt], a[mt], &b[(nt >> 1) * 4 + (nt & 1) * 2]);
    }

    #pragma unroll
    for (int mt = 0; mt < 4; ++mt) {
        int qb = qt * 128 + m0w + mt * 16 + (lane >> 2);
        #pragma unroll
        for (int nt = 0; nt < 4; ++nt) {
            int k0 = kt * 128 + n0w + nt * 8 + (lane & 3) * 2;
            if (k0 >= LP) continue;
            #pragma unroll
            for (int hf = 0; hf < 2; ++hf) {
                int q = qb + hf * 8;
                __half2 e = __floats2half2_rn(C[mt][nt][hf * 2 + 0],
                                              C[mt][nt][hf * 2 + 1]);
                *(__half2*)(g_att + ((size_t)(ng * TT + q)) * LP + k0) = e;
            }
        }
    }
}

// ------- pre-mix(+recomputed ALiBi) -> mask -> softmax -> post-mix ---------
// (R13-verified structure; pass 3 max/exp scans float4-vectorized)
__global__ void __launch_bounds__(256, 4) softmax_kernel(
                               const float* __restrict__ pre,
                               const float* __restrict__ post,
                               const int* __restrict__ seq_mask) {
    __shared__ float sm[8][LP];
    __shared__ float ps_pre[64];
    __shared__ float ps_post[64];
    __shared__ float inv_s[8];
    const int nq = blockIdx.x;
    const int n = nq >> 10, q = nq & 1023;
    const int tid = threadIdx.x;

    if (tid < 64) { ps_pre[tid] = pre[tid]; ps_post[tid] = post[tid]; }

    for (int i8 = tid; i8 < 8 * (LP / 8); i8 += 256) {
        int h = i8 / (LP / 8), kk8 = (i8 - h * (LP / 8)) * 8;
        const __half2* src = (const __half2*)(g_att + ((size_t)((n * 8 + h) * TT + q)) * LP + kk8);
        #pragma unroll
        for (int u = 0; u < 4; ++u) {
            float2 f = __half22float2(src[u]);
            sm[h][kk8 + u * 2 + 0] = f.x;
            sm[h][kk8 + u * 2 + 1] = f.y;
        }
    }
    __syncthreads();

    float spre[8];
    #pragma unroll
    for (int g = 0; g < 8; g++) {
        float s = 0.f;
        #pragma unroll
        for (int h = 0; h < 8; h++) s += ps_pre[g * 8 + h] * exp2f(-(float)(h + 1));
        spre[g] = s;
    }

    const float fq = (float)q;
    for (int kk0 = tid * 4; kk0 < LP; kk0 += 1024) {
        float4 a[8];
        #pragma unroll
        for (int h = 0; h < 8; h++) a[h] = *(const float4*)&sm[h][kk0];
        int4 msk = make_int4(1, 1, 1, 1);
        float4 dist = make_float4(0.f, 0.f, 0.f, 0.f);
        if (kk0 < TT) {
            msk = *(const int4*)(seq_mask + n * TT + kk0);
            dist.x = fabsf(fq - (float)(kk0 + 0));
            dist.y = fabsf(fq - (float)(kk0 + 1));
            dist.z = fabsf(fq - (float)(kk0 + 2));
            dist.w = fabsf(fq - (float)(kk0 + 3));
        }
        #pragma unroll
        for (int g = 0; g < 8; g++) {
            float4 o = make_float4(0.f, 0.f, 0.f, 0.f);
            #pragma unroll
            for (int h = 0; h < 8; h++) {
                float w = ps_pre[g * 8 + h];
                o.x += w * a[h].x; o.y += w * a[h].y;
                o.z += w * a[h].z; o.w += w * a[h].w;
            }
            float sg = spre[g];
            o.x = msk.x ? (o.x - dist.x * sg) * SOFTMAX_SCALE : -442.f;
            o.y = msk.y ? (o.y - dist.y * sg) * SOFTMAX_SCALE : -442.f;
            o.z = msk.z ? (o.z - dist.z * sg) * SOFTMAX_SCALE : -442.f;
            o.w = msk.w ? (o.w - dist.w * sg) * SOFTMAX_SCALE : -442.f;
            *(float4*)&sm[g][kk0] = o;
        }
    }
    __syncthreads();

    // warp w: row max (float4) -> exp + sum (float4, in place)
    const int w = tid >> 5, lane = tid & 31;
    float mx = -1e30f;
    for (int kk = lane * 4; kk < LP; kk += 128) {
        float4 v = *(const float4*)&sm[w][kk];
        mx = fmaxf(mx, fmaxf(fmaxf(v.x, v.y), fmaxf(v.z, v.w)));
    }
    #pragma unroll
    for (int o = 16; o; o >>= 1) mx = fmaxf(mx, __shfl_xor_sync(0xffffffffu, mx, o));
    float s = 0.f;
    for (int kk = lane * 4; kk < LP; kk += 128) {
        float4 v = *(const float4*)&sm[w][kk];
        v.x = __expf(v.x - mx);
        v.y = __expf(v.y - mx);
        v.z = __expf(v.z - mx);
        v.w = __expf(v.w - mx);
        *(float4*)&sm[w][kk] = v;
        s += v.x + v.y + v.z + v.w;
    }
    #pragma unroll
    for (int o = 16; o; o >>= 1) s += __shfl_xor_sync(0xffffffffu, s, o);
    if (lane == 0) inv_s[w] = 1.f / s;
    __syncthreads();

    float inv[8];
    #pragma unroll
    for (int h = 0; h < 8; h++) inv[h] = inv_s[h];
    for (int kk0 = tid * 4; kk0 < LPAD; kk0 += 1024) {
        float4 a[8];
        if (kk0 < LP) {
            #pragma unroll
            for (int h = 0; h < 8; h++) {
                a[h] = *(const float4*)&sm[h][kk0];
                a[h].x *= inv[h]; a[h].y *= inv[h];
                a[h].z *= inv[h]; a[h].w *= inv[h];
            }
        } else {
            #pragma unroll
            for (int h = 0; h < 8; h++) a[h] = make_float4(0.f, 0.f, 0.f, 0.f);
        }
        #pragma unroll
        for (int g = 0; g < 8; g++) {
            float4 o = make_float4(0.f, 0.f, 0.f, 0.f);
            #pragma unroll
            for (int h = 0; h < 8; h++) {
                float wgt = ps_post[g * 8 + h];
                o.x += wgt * a[h].x; o.y += wgt * a[h].y;
                o.z += wgt * a[h].z; o.w += wgt * a[h].w;
            }
            __half2 h01 = __floats2half2_rn(o.x, o.y);
            __half2 h23 = __floats2half2_rn(o.z, o.w);
            __half2* dst = (__half2*)(g_a + ((size_t)((n * 8 + g) * TT + q)) * LPAD + kk0);
            dst[0] = h01;
            dst[1] = h23;
        }
    }
}

// ------------------------- attn @ V (fp16 HMMA) -----------------------------
#define V_A 0
#define V_B 16384
#define V_BUF 24576
#define AV_SMEM (2 * V_BUF)

__global__ void __launch_bounds__(256, 2) av_hmma_kernel() {
    extern __shared__ char smem[];
    const uint32_t sbase = smem_u32(smem);
    const int tid = threadIdx.x;
    const int lane = tid & 31, wid = tid >> 5;
    const int qt = blockIdx.x;          // 8
    const int ng = blockIdx.y;          // 64
    const int m0w = (wid & 3) * 32;
    const int n0w = (wid >> 2) * 32;

    float C[2][4][4];
    #pragma unroll
    for (int mt = 0; mt < 2; ++mt)
        #pragma unroll
        for (int nt = 0; nt < 4; ++nt)
            #pragma unroll
            for (int i = 0; i < 4; ++i) C[mt][nt][i] = 0.f;

    auto load_chunk = [&](int c, uint32_t bb) {
        #pragma unroll
        for (int it = 0; it < 4; ++it) {
            int s = it * 256 + tid;
            int r = s >> 3, cb = s & 7;
            size_t ga = ((size_t)ng * TT + qt * 128 + r) * LPAD + c * 64 + cb * 8;
            cpasync16(bb + V_A + SWZ((uint32_t)(r * 128 + cb * 16)), g_a + ga);
        }
        #pragma unroll
        for (int it = 0; it < 2; ++it) {
            int s = it * 256 + tid;
            int r = s >> 3, cb = s & 7;
            size_t gb = ((size_t)ng * 64 + r) * LPAD + c * 64 + cb * 8;
            cpasync16(bb + V_B + SWZ((uint32_t)(r * 128 + cb * 16)), g_vT + gb);
        }
        cp_commit();
    };

    load_chunk(0, sbase);

    for (int c = 0; c < 17; ++c) {
        const bool hn = (c + 1 < 17);
        if (hn) load_chunk(c + 1, sbase + ((c + 1) & 1) * V_BUF);
        if (hn) cp_wait1(); else cp_wait0();
        __syncthreads();

        const uint32_t Ab = sbase + (c & 1) * V_BUF;
        #pragma unroll
        for (int ks = 0; ks < 4; ++ks) {
            uint32_t a[2][4];
            #pragma unroll
            for (int mt = 0; mt < 2; ++mt) {
                uint32_t off = SWZ((uint32_t)((m0w + mt * 16 + (lane & 15)) * 128
                                              + ks * 32 + (lane >> 4) * 16));
                ldsm4(a[mt], Ab + V_A + off);
            }
            uint32_t b[8];
            #pragma unroll
            for (int p = 0; p < 2; ++p) {
                uint32_t off = SWZ((uint32_t)((n0w + p * 16 + (lane & 7) + ((lane >> 4) & 1) * 8) * 128
                                              + ks * 32 + ((lane >> 3) & 1) * 16));
                ldsm4(&b[p * 4], Ab + V_B + off);
            }
            #pragma unroll
            for (int mt = 0; mt < 2; ++mt)
                #pragma unroll
                for (int nt = 0; nt < 4; ++nt)
                    mma_f16(C[mt][nt], a[mt], &b[(nt >> 1) * 4 + (nt & 1) * 2]);
        }
        __syncthreads();
    }

    const int n = ng >> 3, h = ng & 7;
    #pragma unroll
    for (int mt = 0; mt < 2; ++mt) {
        int qb = qt * 128 + m0w + mt * 16 + (lane >> 2);
        #pragma unroll
        for (int nt = 0; nt < 4; ++nt) {
            int dcol = n0w + nt * 8 + (lane & 3) * 2;
            #pragma unroll
            for (int hf = 0; hf < 2; ++hf) {
                int q = qb + hf * 8;
                size_t o = ((size_t)(n * TT + q)) * 512 + h * 64 + dcol;
                *(__half2*)(g_ctx + o) =
                    __floats2half2_rn(C[mt][nt][hf * 2 + 0], C[mt][nt][hf * 2 + 1]);
            }
        }
    }
}

// ------------------------- LayerNorm (warp per row) -------------------------
__global__ void __launch_bounds__(256) ln_kernel(
                          const float* __restrict__ gamma,
                          const float* __restrict__ beta,
                          float* __restrict__ out) {
    const int lane = threadIdx.x & 31, wid = threadIdx.x >> 5;
    const int r = blockIdx.x * 8 + wid;
    const float* in = g_t2 + (size_t)r * EE;

    float4 v[4];
    float s = 0.f;
    #pragma unroll
    for (int i = 0; i < 4; ++i) {
        v[i] = *(const float4*)(in + i * 128 + lane * 4);
        s += v[i].x + v[i].y + v[i].z + v[i].w;
    }
    #pragma unroll
    for (int o = 16; o; o >>= 1) s += __shfl_xor_sync(0xffffffffu, s, o);
    float mu = s * (1.f / EE);

    float vs = 0.f;
    #pragma unroll
    for (int i = 0; i < 4; ++i) {
        float dx = v[i].x - mu, dy = v[i].y - mu, dz = v[i].z - mu, dw = v[i].w - mu;
        vs += dx * dx + dy * dy + dz * dz + dw * dw;
    }
    #pragma unroll
    for (int o = 16; o; o >>= 1) vs += __shfl_xor_sync(0xffffffffu, vs, o);
    float inv = rsqrtf(vs * (1.f / EE) + 1e-5f);

    #pragma unroll
    for (int i = 0; i < 4; ++i) {
        int col = i * 128 + lane * 4;
        float4 g = *(const float4*)(gamma + col);
        float4 b = *(const float4*)(beta + col);
        float4 o;
        o.x = (v[i].x - mu) * inv * g.x + b.x;
        o.y = (v[i].y - mu) * inv * g.y + b.y;
        o.z = (v[i].z - mu) * inv * g.z + b.z;
        o.w = (v[i].w - mu) * inv * g.w + b.w;
        *(float4*)(out + (size_t)r * EE + col) = o;
    }
}

// ------------------------------ launcher -----------------------------------
extern "C" void kernel_launch(void* const* d_in, const int* in_sizes, int n_in,
                              void* d_out, int out_size) {
    const float* x        = (const float*)d_in[0];
    const int*   seq_mask = (const int*)  d_in[1];
    const float* Wq       = (const float*)d_in[2];
    const float* Wk       = (const float*)d_in[3];
    const float* Wv       = (const float*)d_in[4];
    const float* Wo       = (const float*)d_in[5];
    const float* bo       = (const float*)d_in[6];
    const float* pre_th   = (const float*)d_in[7];
    const float* post_th  = (const float*)d_in[8];
    const float* pk       = (const float*)d_in[9];
    const float* pv       = (const float*)d_in[10];
    const float* c1W      = (const float*)d_in[11];
    const float* c1b      = (const float*)d_in[12];
    const float* c2W      = (const float*)d_in[13];
    const float* c2b      = (const float*)d_in[14];
    const float* ln_g     = (const float*)d_in[15];
    const float* ln_b     = (const float*)d_in[16];
    float* out = (float*)d_out;

    __half *pWo, *pC1, *pC2, *pCtx, *pH, *pT1;
    float *pT2;
    cudaGetSymbolAddress((void**)&pWo,  g_Wo);
    cudaGetSymbolAddress((void**)&pC1,  g_c1);
    cudaGetSymbolAddress((void**)&pC2,  g_c2);
    cudaGetSymbolAddress((void**)&pCtx, g_ctx);
    cudaGetSymbolAddress((void**)&pH,   g_h);
    cudaGetSymbolAddress((void**)&pT1,  g_t1);
    cudaGetSymbolAddress((void**)&pT2,  g_t2);

    cudaFuncSetAttribute(gemm_hmma_kernel,
                         cudaFuncAttributeMaxDynamicSharedMemorySize, GEMM_SMEM);
    cudaFuncSetAttribute(energy_hmma_kernel,
                         cudaFuncAttributeMaxDynamicSharedMemorySize, EGY_SMEM);
    cudaFuncSetAttribute(av_hmma_kernel,
                         cudaFuncAttributeMaxDynamicSharedMemorySize, AV_SMEM);
    cudaFuncSetAttribute(qkv_hmma_kernel,
                         cudaFuncAttributeMaxDynamicSharedMemorySize, QKV_SMEM);

    wo_convert<<<1024, 256>>>(Wo, pWo);
    conv_w_convert<<<3072, 256>>>(c1W, pC1);
    conv_w_convert<<<3072, 256>>>(c2W, pC2);

    qkv_hmma_kernel<<<dim3(64, 8), 256, QKV_SMEM>>>(x, Wq, Wk, Wv);
    persist_pad_kernel<<<2816, 256>>>(pk, pv);

    energy_hmma_kernel<<<dim3(8, 9, 64), 256, EGY_SMEM>>>();
    softmax_kernel<<<8192, 256>>>(pre_th, post_th, seq_mask);
    av_hmma_kernel<<<dim3(8, 64), 256, AV_SMEM>>>();

    gemm_hmma_kernel<<<dim3(64, 4), 256, GEMM_SMEM>>>(
        0, 8, pCtx, pWo, bo, x, nullptr, seq_mask, pH);
    gemm_hmma_kernel<<<dim3(64, 4), 256, GEMM_SMEM>>>(
        1, 24, pH, pC1, c1b, nullptr, nullptr, seq_mask, pT1);
    gemm_hmma_kernel<<<dim3(64, 4), 256, GEMM_SMEM>>>(
        2, 24, pT1, pC2, c2b, nullptr, pH, seq_mask, pT2);

    ln_kernel<<<1024, 256>>>(ln_g, ln_b, out);
}

// round 17
// speedup vs baseline: 1.5993x; 1.0122x over previous
#include <cuda_runtime.h>
#include <cuda_bf16.h>
#include <cuda_fp16.h>
#include <math.h>
#include <stdint.h>

// ---------------------------------------------------------------------------
// TCNAttentionBlock. R17 = R16 resubmit (infra failure, no signal):
// energy with Q-resident kt-loop + av with M=256 tile. Softmax R13/R15 form.
// N=8, T=1024, E=512, H=8, D=64, P=16.
// ---------------------------------------------------------------------------

#define NB   8
#define TT   1024
#define EE   512
#define HH   8
#define DD   64
#define PP   16
#define LP   1040            // TT + PP
#define LPAD 1088            // attn row padded (17 chunks of 64)
#define KPAD 1152            // K rows padded (9 tiles of 128)
#define SOFTMAX_SCALE 0.044194173824159216f   // 1/sqrt(512)

// ------------------------------ scratch -----------------------------------
__device__ __half g_q  [64 * TT * DD];                     // fp16 [ng][q][64]
__device__ __half g_k  [64 * KPAD * DD];                   // fp16 [ng][l][64]
__device__ __half g_vT [64 * DD * LPAD];                   // fp16 [ng][d][1088]
__device__ __half g_att[(size_t)64 * TT * LP];             // fp16 raw QK^T
__device__ __half g_a  [(size_t)64 * TT * LPAD];           // fp16 attn
__device__ __half g_ctx[NB * TT * EE];                     // fp16
__device__ __half g_h  [NB * TT * EE];                     // fp16 (x + att)
__device__ __half g_t1 [NB * TT * EE];                     // fp16
__device__ float  g_t2 [NB * TT * EE];                     // fp32

// preconverted fp16 weights, layout [chunk][co(512)][64]
__device__ __half g_Wo[8  * 512 * 64];
__device__ __half g_c1[24 * 512 * 64];
__device__ __half g_c2[24 * 512 * 64];

// ---------------------------- PTX helpers ----------------------------------
__device__ __forceinline__ uint32_t smem_u32(const void* p) {
    uint32_t a;
    asm("{ .reg .u64 t; cvta.to.shared.u64 t, %1; cvt.u32.u64 %0, t; }"
        : "=r"(a) : "l"(p));
    return a;
}
#define SWZ(o) ((o) ^ (((o) >> 3) & 0x70))

__device__ __forceinline__ void ldsm4(uint32_t* r, uint32_t addr) {
    asm volatile("ldmatrix.sync.aligned.m8n8.x4.shared.b16 {%0,%1,%2,%3}, [%4];"
                 : "=r"(r[0]), "=r"(r[1]), "=r"(r[2]), "=r"(r[3]) : "r"(addr));
}
__device__ __forceinline__ void mma_f16(float* c, const uint32_t* a, const uint32_t* b) {
    asm volatile(
        "mma.sync.aligned.m16n8k16.row.col.f32.f16.f16.f32 "
        "{%0,%1,%2,%3}, {%4,%5,%6,%7}, {%8,%9}, {%0,%1,%2,%3};"
        : "+f"(c[0]), "+f"(c[1]), "+f"(c[2]), "+f"(c[3])
        : "r"(a[0]), "r"(a[1]), "r"(a[2]), "r"(a[3]), "r"(b[0]), "r"(b[1]));
}
__device__ __forceinline__ void cpasync16(uint32_t saddr, const void* g) {
    asm volatile("cp.async.cg.shared.global [%0], [%1], 16;" :: "r"(saddr), "l"(g));
}
__device__ __forceinline__ void cpasync16z(uint32_t saddr, const void* g, int sz) {
    asm volatile("cp.async.cg.shared.global [%0], [%1], 16, %2;"
                 :: "r"(saddr), "l"(g), "r"(sz));
}
__device__ __forceinline__ void cp_commit() {
    asm volatile("cp.async.commit_group;" ::: "memory");
}
__device__ __forceinline__ void cp_wait0() {
    asm volatile("cp.async.wait_group 0;" ::: "memory");
}
__device__ __forceinline__ void cp_wait1() {
    asm volatile("cp.async.wait_group 1;" ::: "memory");
}
__device__ __forceinline__ uint32_t tf32r_u(float v) {   // for A staging in qkv
    uint32_t u;
    asm("cvt.rna.tf32.f32 %0, %1;" : "=r"(u) : "f"(v));
    return u;
}
__device__ __forceinline__ void mma_tf32(float* c, const uint32_t* a, const uint32_t* b) {
    asm volatile(
        "mma.sync.aligned.m16n8k8.row.col.f32.tf32.tf32.f32 "
        "{%0,%1,%2,%3}, {%4,%5,%6,%7}, {%8,%9}, {%0,%1,%2,%3};"
        : "+f"(c[0]), "+f"(c[1]), "+f"(c[2]), "+f"(c[3])
        : "r"(a[0]), "r"(a[1]), "r"(a[2]), "r"(a[3]), "r"(b[0]), "r"(b[1]));
}

// ---------------------- weight preconversion (fp16) -------------------------
__global__ void conv_w_convert(const float* __restrict__ W, __half* __restrict__ o) {
    int d = blockIdx.x * 256 + threadIdx.x;          // 24*512*64 = 786432
    int c  = d >> 15;
    int co = (d >> 6) & 511;
    int ci = d & 63;
    int tap = c >> 3, cib = (c & 7) << 6;
    o[d] = __float2half(W[(size_t)(co * 512 + cib + ci) * 3 + tap]);
}
__global__ void wo_convert(const float* __restrict__ W, __half* __restrict__ o) {
    int d = blockIdx.x * 256 + threadIdx.x;          // 8*512*64 = 262144
    int c  = d >> 15;
    int co = (d >> 6) & 511;
    int ci = d & 63;
    o[d] = __float2half(W[co * 512 + (c << 6) + ci]);
}

// ------------------------ QKV on tf32 HMMA ----------------------------------
#define QKV_B0 32768
#define QKV_SMEM (32768 + 3 * 16384)
__global__ void __launch_bounds__(256, 2) qkv_hmma_kernel(
    const float* __restrict__ x,
    const float* __restrict__ Wq,
    const float* __restrict__ Wk,
    const float* __restrict__ Wv)
{
    extern __shared__ char smem[];
    const uint32_t sbase = smem_u32(smem);
    const int tid = threadIdx.x;
    const int lane = tid & 31, wid = tid >> 5;
    const int t0 = blockIdx.x * 128;
    const int h  = blockIdx.y;
    const int n  = t0 >> 10;
    const int ng = n * 8 + h;
    const int m0w = (wid & 3) * 32;
    const int n0w = (wid >> 2) * 32;

    #pragma unroll
    for (int it = 0; it < 8; ++it) {
        int lin = it * 1024 + tid * 4;
        int r = lin >> 6, ci = lin & 63;
        float4 v = *(const float4*)(x + (size_t)(t0 + r) * 512 + h * 64 + ci);
        uint32_t off = (ci >> 5) * 16384 + SWZ((uint32_t)(r * 128 + (ci & 31) * 4));
        *(uint4*)(smem + off) = make_uint4(tf32r_u(v.x), tf32r_u(v.y),
                                           tf32r_u(v.z), tf32r_u(v.w));
    }
    #pragma unroll
    for (int m = 0; m < 3; ++m) {
        const float* Wm = (m == 0) ? Wq : (m == 1) ? Wk : Wv;
        #pragma unroll
        for (int it = 0; it < 4; ++it) {
            int lin = it * 1024 + tid * 4;
            int r = lin >> 6, ci = lin & 63;
            float4 v = *(const float4*)(Wm + r * 64 + ci);
            uint32_t off = QKV_B0 + m * 16384 + (ci >> 5) * 8192
                         + SWZ((uint32_t)(r * 128 + (ci & 31) * 4));
            *(uint4*)(smem + off) = make_uint4(tf32r_u(v.x), tf32r_u(v.y),
                                               tf32r_u(v.z), tf32r_u(v.w));
        }
    }
    __syncthreads();

    for (int m = 0; m < 3; ++m) {
        float C[2][4][4];
        #pragma unroll
        for (int mt = 0; mt < 2; ++mt)
            #pragma unroll
            for (int nt = 0; nt < 4; ++nt)
                #pragma unroll
                for (int i = 0; i < 4; ++i) C[mt][nt][i] = 0.f;

        const uint32_t bbase = sbase + QKV_B0 + m * 16384;
        #pragma unroll
        for (int panel = 0; panel < 2; ++panel) {
            #pragma unroll
            for (int ks = 0; ks < 4; ++ks) {
                uint32_t a[2][4];
                #pragma unroll
                for (int mt = 0; mt < 2; ++mt) {
                    uint32_t off = panel * 16384
                        + SWZ((uint32_t)((m0w + mt * 16 + (lane & 15)) * 128
                                         + ks * 32 + (lane >> 4) * 16));
                    ldsm4(a[mt], sbase + off);
                }
                uint32_t b[8];
                #pragma unroll
                for (int p = 0; p < 2; ++p) {
                    uint32_t off = panel * 8192
                        + SWZ((uint32_t)((n0w + p * 16 + (lane & 7) + ((lane >> 4) & 1) * 8) * 128
                                         + ks * 32 + ((lane >> 3) & 1) * 16));
                    ldsm4(&b[p * 4], bbase + off);
                }
                #pragma unroll
                for (int mt = 0; mt < 2; ++mt)
                    #pragma unroll
                    for (int nt = 0; nt < 4; ++nt)
                        mma_tf32(C[mt][nt], a[mt], &b[(nt >> 1) * 4 + (nt & 1) * 2]);
            }
        }

        #pragma unroll
        for (int mt = 0; mt < 2; ++mt) {
            int tb = t0 + m0w + mt * 16 + (lane >> 2);
            #pragma unroll
            for (int nt = 0; nt < 4; ++nt) {
                int col = n0w + nt * 8 + (lane & 3) * 2;
                #pragma unroll
                for (int hf = 0; hf < 2; ++hf) {
                    int ts = (tb + hf * 8) & 1023;
                    float y0 = C[mt][nt][hf * 2 + 0];
                    float y1 = C[mt][nt][hf * 2 + 1];
                    if (m == 0) {
                        size_t o = ((size_t)ng * TT + ts) * 64 + col;
                        *(__half2*)(g_q + o) = __floats2half2_rn(y0, y1);
                    } else if (m == 1) {
                        size_t o = ((size_t)ng * KPAD + ts) * 64 + col;
                        *(__half2*)(g_k + o) = __floats2half2_rn(y0, y1);
                    } else {
                        g_vT[((size_t)ng * 64 + col)     * LPAD + ts] = __float2half(y0);
                        g_vT[((size_t)ng * 64 + col + 1) * LPAD + ts] = __float2half(y1);
                    }
                }
            }
        }
    }
}

// ---------------------- fp16 HMMA GEMM (outproj / conv) ---------------------
#define G_A 0
#define G_B 16384
#define G_BUF 32768
#define GEMM_SMEM (2 * G_BUF)

__global__ void __launch_bounds__(256, 2) gemm_hmma_kernel(
    int mode, int nchunk,
    const __half* __restrict__ IN,
    const __half* __restrict__ Bg,
    const float* __restrict__ bias,
    const float* __restrict__ residf,
    const __half* __restrict__ residh,
    const int* __restrict__ seq_mask,
    void* __restrict__ OUTv)
{
    extern __shared__ char smem[];
    const uint32_t sbase = smem_u32(smem);
    const int tid = threadIdx.x;
    const int lane = tid & 31, wid = tid >> 5;
    const int t0 = blockIdx.x * 128;
    const int co0 = blockIdx.y * 128;
    const int nBseq = t0 & ~1023;
    const int m0w = (wid & 1) * 64;
    const int n0w = (wid >> 1) * 32;

    float C[4][4][4];
    #pragma unroll
    for (int mt = 0; mt < 4; ++mt)
        #pragma unroll
        for (int nt = 0; nt < 4; ++nt)
            #pragma unroll
            for (int i = 0; i < 4; ++i) C[mt][nt][i] = 0.f;

    auto load_chunk = [&](int c, uint32_t bb) {
        int shift, cib;
        if (mode == 0) { shift = 0; cib = c << 6; }
        else           { shift = (c >> 3) - 2; cib = (c & 7) << 6; }
        #pragma unroll
        for (int it = 0; it < 4; ++it) {
            int s = it * 256 + tid;
            int r = s >> 3, cb = s & 7;
            int grow = t0 + r + shift;
            int ok = (grow >= nBseq);
            int ga = ok ? grow : nBseq;
            cpasync16z(bb + G_A + SWZ((uint32_t)(r * 128 + cb * 16)),
                       IN + (size_t)ga * 512 + cib + cb * 8, ok ? 16 : 0);
        }
        #pragma unroll
        for (int it = 0; it < 4; ++it) {
            int s = it * 256 + tid;
            int r = s >> 3, cb = s & 7;
            size_t gb = ((size_t)(c * 512 + co0 + r) << 6) + cb * 8;
            cpasync16(bb + G_B + SWZ((uint32_t)(r * 128 + cb * 16)), Bg + gb);
        }
        cp_commit();
    };

    load_chunk(0, sbase);

    for (int c = 0; c < nchunk; ++c) {
        const bool hn = (c + 1 < nchunk);
        if (hn) load_chunk(c + 1, sbase + ((c + 1) & 1) * G_BUF);
        if (hn) cp_wait1(); else cp_wait0();
        __syncthreads();

        const uint32_t Ab = sbase + (c & 1) * G_BUF;
        #pragma unroll
        for (int ks = 0; ks < 4; ++ks) {
            uint32_t a[4][4];
            #pragma unroll
            for (int mt = 0; mt < 4; ++mt) {
                uint32_t off = SWZ((uint32_t)((m0w + mt * 16 + (lane & 15)) * 128
                                              + ks * 32 + (lane >> 4) * 16));
                ldsm4(a[mt], Ab + G_A + off);
            }
            uint32_t b[8];
            #pragma unroll
            for (int p = 0; p < 2; ++p) {
                uint32_t off = SWZ((uint32_t)((n0w + p * 16 + (lane & 7) + ((lane >> 4) & 1) * 8) * 128
                                              + ks * 32 + ((lane >> 3) & 1) * 16));
                ldsm4(&b[p * 4], Ab + G_B + off);
            }
            #pragma unroll
            for (int mt = 0; mt < 4; ++mt)
                #pragma unroll
                for (int nt = 0; nt < 4; ++nt)
                    mma_f16(C[mt][nt], a[mt], &b[(nt >> 1) * 4 + (nt & 1) * 2]);
        }
        __syncthreads();
    }

    #pragma unroll
    for (int mt = 0; mt < 4; ++mt) {
        int rb = t0 + m0w + mt * 16 + (lane >> 2);
        #pragma unroll
        for (int nt = 0; nt < 4; ++nt) {
            int col = co0 + n0w + nt * 8 + (lane & 3) * 2;
            float b0 = bias[col], b1 = bias[col + 1];
            #pragma unroll
            for (int hf = 0; hf < 2; ++hf) {
                int r = rb + hf * 8;
                float y0 = C[mt][nt][hf * 2 + 0] + b0;
                float y1 = C[mt][nt][hf * 2 + 1] + b1;
                if (mode == 0) {
                    const float2 rs = *(const float2*)(residf + (size_t)r * 512 + col);
                    *(__half2*)((__half*)OUTv + (size_t)r * 512 + col) =
                        __floats2half2_rn(y0 + rs.x, y1 + rs.y);
                } else {
                    float valid = (float)seq_mask[r];
                    y0 = fmaxf(y0 * valid, 0.f);
                    y1 = fmaxf(y1 * valid, 0.f);
                    if (mode == 2) {
                        float2 rs = __half22float2(
                            *(const __half2*)(residh + (size_t)r * 512 + col));
                        y0 = fmaxf(y0 + rs.x, 0.f);
                        y1 = fmaxf(y1 + rs.y, 0.f);
                        *(float2*)((float*)OUTv + (size_t)r * 512 + col) =
                            make_float2(y0, y1);
                    } else {
                        *(__half2*)((__half*)OUTv + (size_t)r * 512 + col) =
                            __floats2half2_rn(y0, y1);
                    }
                }
            }
        }
    }
}

// ------- persistent kv slots (k + vT) + k padding + vT padding -------------
__global__ void persist_pad_kernel(const float* __restrict__ pk,
                                   const float* __restrict__ pv) {
    int idx = blockIdx.x * 256 + threadIdx.x;
    if (idx < NB * PP * HH * DD) {                      // 65536
        int d = idx & 63, h = (idx >> 6) & 7, p = (idx >> 9) & 15, n = idx >> 13;
        int src = ((p * HH + h) << 6) + d;
        int ng = n * 8 + h;
        g_vT[((size_t)ng * 64 + d) * LPAD + TT + p] = __float2half(pv[src]);
        g_k[((size_t)ng * KPAD + TT + p) * 64 + d] = __float2half(pk[src]);
        return;
    }
    int j = idx - NB * PP * HH * DD;
    if (j < 64 * 112 * 64) {                            // k pad rows [LP,KPAD)
        int d = j & 63;
        int l = LP + ((j >> 6) % 112);
        int ng = j / (112 * 64);
        g_k[((size_t)ng * KPAD + l) * 64 + d] = __float2half(0.f);
        return;
    }
    j -= 64 * 112 * 64;
    if (j < 64 * 64 * 48) {                             // vT pad cols [LP,LPAD)
        int c = j % 48;
        int d = (j / 48) & 63;
        int ng = j / (48 * 64);
        g_vT[((size_t)ng * 64 + d) * LPAD + LP + c] = __float2half(0.f);
    }
}

// ------ energy: Q resident, kt-loop with double-buffered K (fp16 HMMA) ------
#define E_Q 0
#define E_K 16384
#define E_KBUF 16384
#define EGY_SMEM (16384 + 2 * 16384)
__global__ void __launch_bounds__(256, 2) energy_hmma_kernel() {
    extern __shared__ char smem[];
    const uint32_t sbase = smem_u32(smem);
    const int tid = threadIdx.x;
    const int lane = tid & 31, wid = tid >> 5;
    const int qt = blockIdx.x;          // 8
    const int ng = blockIdx.y;          // 64
    const int m0w = (wid & 1) * 64;
    const int n0w = (wid >> 1) * 32;

    // load Q (once) + K(0)
    #pragma unroll
    for (int it = 0; it < 4; ++it) {
        int s = it * 256 + tid;
        int r = s >> 3, cb = s & 7;
        uint32_t off = SWZ((uint32_t)(r * 128 + cb * 16));
        size_t qa = ((size_t)ng * TT + qt * 128 + r) * 64 + cb * 8;
        size_t ka = ((size_t)ng * KPAD + r) * 64 + cb * 8;
        cpasync16(sbase + E_Q + off, g_q + qa);
        cpasync16(sbase + E_K + off, g_k + ka);
    }
    cp_commit();

    for (int kt = 0; kt < 9; ++kt) {
        const bool hn = (kt + 1 < 9);
        if (hn) {
            uint32_t kb = sbase + E_K + ((kt + 1) & 1) * E_KBUF;
            #pragma unroll
            for (int it = 0; it < 4; ++it) {
                int s = it * 256 + tid;
                int r = s >> 3, cb = s & 7;
                size_t ka = ((size_t)ng * KPAD + (kt + 1) * 128 + r) * 64 + cb * 8;
                cpasync16(kb + SWZ((uint32_t)(r * 128 + cb * 16)), g_k + ka);
            }
            cp_commit();
        }
        if (hn) cp_wait1(); else cp_wait0();
        __syncthreads();

        const uint32_t Kb = sbase + E_K + (kt & 1) * E_KBUF;
        float C[4][4][4];
        #pragma unroll
        for (int mt = 0; mt < 4; ++mt)
            #pragma unroll
            for (int nt = 0; nt < 4; ++nt)
                #pragma unroll
                for (int i = 0; i < 4; ++i) C[mt][nt][i] = 0.f;

        #pragma unroll
        for (int ks = 0; ks < 4; ++ks) {
            uint32_t a[4][4];
            #pragma unroll
            for (int mt = 0; mt < 4; ++mt) {
                uint32_t off = SWZ((uint32_t)((m0w + mt * 16 + (lane & 15)) * 128
                                              + ks * 32 + (lane >> 4) * 16));
                ldsm4(a[mt], sbase + E_Q + off);
            }
            uint32_t b[8];
            #pragma unroll
            for (int p = 0; p < 2; ++p) {
                uint32_t off = SWZ((uint32_t)((n0w + p * 16 + (lane & 7) + ((lane >> 4) & 1) * 8) * 128
                                              + ks * 32 + ((lane >> 3) & 1) * 16));
                ldsm4(&b[p * 4], Kb + off);
            }
            #pragma unroll
            for (int mt = 0; mt < 4; ++mt)
                #pragma unroll
                for (int nt = 0; nt < 4; ++nt)
                    mma_f16(C[mt][nt], a[mt], &b[(nt >> 1) * 4 + (nt & 1) * 2]);
        }

        #pragma unroll
        for (int mt = 0; mt < 4; ++mt) {
            int qb = qt * 128 + m0w + mt * 16 + (lane >> 2);
            #pragma unroll
            for (int nt = 0; nt < 4; ++nt) {
                int k0 = kt * 128 + n0w + nt * 8 + (lane & 3) * 2;
                if (k0 >= LP) continue;
                #pragma unroll
                for (int hf = 0; hf < 2; ++hf) {
                    int q = qb + hf * 8;
                    __half2 e = __floats2half2_rn(C[mt][nt][hf * 2 + 0],
                                                  C[mt][nt][hf * 2 + 1]);
                    *(__half2*)(g_att + ((size_t)(ng * TT + q)) * LP + k0) = e;
                }
            }
        }
        __syncthreads();
    }
}

// ------- pre-mix(+recomputed ALiBi) -> mask -> softmax -> post-mix ---------
// (R13/R15-verified structure; exp stays in the per-warp pass)
__global__ void __launch_bounds__(256, 4) softmax_kernel(
                               const float* __restrict__ pre,
                               const float* __restrict__ post,
                               const int* __restrict__ seq_mask) {
    __shared__ float sm[8][LP];
    __shared__ float ps_pre[64];
    __shared__ float ps_post[64];
    __shared__ float inv_s[8];
    const int nq = blockIdx.x;
    const int n = nq >> 10, q = nq & 1023;
    const int tid = threadIdx.x;

    if (tid < 64) { ps_pre[tid] = pre[tid]; ps_post[tid] = post[tid]; }

    for (int i8 = tid; i8 < 8 * (LP / 8); i8 += 256) {
        int h = i8 / (LP / 8), kk8 = (i8 - h * (LP / 8)) * 8;
        const __half2* src = (const __half2*)(g_att + ((size_t)((n * 8 + h) * TT + q)) * LP + kk8);
        #pragma unroll
        for (int u = 0; u < 4; ++u) {
            float2 f = __half22float2(src[u]);
            sm[h][kk8 + u * 2 + 0] = f.x;
            sm[h][kk8 + u * 2 + 1] = f.y;
        }
    }
    __syncthreads();

    float spre[8];
    #pragma unroll
    for (int g = 0; g < 8; g++) {
        float s = 0.f;
        #pragma unroll
        for (int h = 0; h < 8; h++) s += ps_pre[g * 8 + h] * exp2f(-(float)(h + 1));
        spre[g] = s;
    }

    const float fq = (float)q;
    for (int kk0 = tid * 4; kk0 < LP; kk0 += 1024) {
        float4 a[8];
        #pragma unroll
        for (int h = 0; h < 8; h++) a[h] = *(const float4*)&sm[h][kk0];
        int4 msk = make_int4(1, 1, 1, 1);
        float4 dist = make_float4(0.f, 0.f, 0.f, 0.f);
        if (kk0 < TT) {
            msk = *(const int4*)(seq_mask + n * TT + kk0);
            dist.x = fabsf(fq - (float)(kk0 + 0));
            dist.y = fabsf(fq - (float)(kk0 + 1));
            dist.z = fabsf(fq - (float)(kk0 + 2));
            dist.w = fabsf(fq - (float)(kk0 + 3));
        }
        #pragma unroll
        for (int g = 0; g < 8; g++) {
            float4 o = make_float4(0.f, 0.f, 0.f, 0.f);
            #pragma unroll
            for (int h = 0; h < 8; h++) {
                float w = ps_pre[g * 8 + h];
                o.x += w * a[h].x; o.y += w * a[h].y;
                o.z += w * a[h].z; o.w += w * a[h].w;
            }
            float sg = spre[g];
            o.x = msk.x ? (o.x - dist.x * sg) * SOFTMAX_SCALE : -442.f;
            o.y = msk.y ? (o.y - dist.y * sg) * SOFTMAX_SCALE : -442.f;
            o.z = msk.z ? (o.z - dist.z * sg) * SOFTMAX_SCALE : -442.f;
            o.w = msk.w ? (o.w - dist.w * sg) * SOFTMAX_SCALE : -442.f;
            *(float4*)&sm[g][kk0] = o;
        }
    }
    __syncthreads();

    const int w = tid >> 5, lane = tid & 31;
    float mx = -1e30f;
    for (int kk = lane * 4; kk < LP; kk += 128) {
        float4 v = *(const float4*)&sm[w][kk];
        mx = fmaxf(mx, fmaxf(fmaxf(v.x, v.y), fmaxf(v.z, v.w)));
    }
    #pragma unroll
    for (int o = 16; o; o >>= 1) mx = fmaxf(mx, __shfl_xor_sync(0xffffffffu, mx, o));
    float s = 0.f;
    for (int kk = lane * 4; kk < LP; kk += 128) {
        float4 v = *(const float4*)&sm[w][kk];
        v.x = __expf(v.x - mx);
        v.y = __expf(v.y - mx);
        v.z = __expf(v.z - mx);
        v.w = __expf(v.w - mx);
        *(float4*)&sm[w][kk] = v;
        s += v.x + v.y + v.z + v.w;
    }
    #pragma unroll
    for (int o = 16; o; o >>= 1) s += __shfl_xor_sync(0xffffffffu, s, o);
    if (lane == 0) inv_s[w] = 1.f / s;
    __syncthreads();

    float inv[8];
    #pragma unroll
    for (int h = 0; h < 8; h++) inv[h] = inv_s[h];
    for (int kk0 = tid * 4; kk0 < LPAD; kk0 += 1024) {
        float4 a[8];
        if (kk0 < LP) {
            #pragma unroll
            for (int h = 0; h < 8; h++) {
                a[h] = *(const float4*)&sm[h][kk0];
                a[h].x *= inv[h]; a[h].y *= inv[h];
                a[h].z *= inv[h]; a[h].w *= inv[h];
            }
        } else {
            #pragma unroll
            for (int h = 0; h < 8; h++) a[h] = make_float4(0.f, 0.f, 0.f, 0.f);
        }
        #pragma unroll
        for (int g = 0; g < 8; g++) {
            float4 o = make_float4(0.f, 0.f, 0.f, 0.f);
            #pragma unroll
            for (int h = 0; h < 8; h++) {
                float wgt = ps_post[g * 8 + h];
                o.x += wgt * a[h].x; o.y += wgt * a[h].y;
                o.z += wgt * a[h].z; o.w += wgt * a[h].w;
            }
            __half2 h01 = __floats2half2_rn(o.x, o.y);
            __half2 h23 = __floats2half2_rn(o.z, o.w);
            __half2* dst = (__half2*)(g_a + ((size_t)((n * 8 + g) * TT + q)) * LPAD + kk0);
            dst[0] = h01;
            dst[1] = h23;
        }
    }
}

// ------------------- attn @ V (fp16 HMMA, M=256 tile) -----------------------
#define V_A 0
#define V_B 32768
#define V_BUF 40960
#define AV_SMEM (2 * V_BUF)

__global__ void __launch_bounds__(256, 2) av_hmma_kernel() {
    extern __shared__ char smem[];
    const uint32_t sbase = smem_u32(smem);
    const int tid = threadIdx.x;
    const int lane = tid & 31, wid = tid >> 5;
    const int qt = blockIdx.x;          // 4 (256-row tiles)
    const int ng = blockIdx.y;          // 64
    const int m0w = wid * 32;           // 8 warps x 32 rows

    float C[2][8][4];
    #pragma unroll
    for (int mt = 0; mt < 2; ++mt)
        #pragma unroll
        for (int nt = 0; nt < 8; ++nt)
            #pragma unroll
            for (int i = 0; i < 4; ++i) C[mt][nt][i] = 0.f;

    auto load_chunk = [&](int c, uint32_t bb) {
        // A: 256 rows x 128B
        #pragma unroll
        for (int it = 0; it < 8; ++it) {
            int s = it * 256 + tid;
            int r = s >> 3, cb = s & 7;
            size_t ga = ((size_t)ng * TT + qt * 256 + r) * LPAD + c * 64 + cb * 8;
            cpasync16(bb + V_A + SWZ((uint32_t)(r * 128 + cb * 16)), g_a + ga);
        }
        // B: 64 rows x 128B
        #pragma unroll
        for (int it = 0; it < 2; ++it) {
            int s = it * 256 + tid;
            int r = s >> 3, cb = s & 7;
            size_t gb = ((size_t)ng * 64 + r) * LPAD + c * 64 + cb * 8;
            cpasync16(bb + V_B + SWZ((uint32_t)(r * 128 + cb * 16)), g_vT + gb);
        }
        cp_commit();
    };

    load_chunk(0, sbase);

    for (int c = 0; c < 17; ++c) {
        const bool hn = (c + 1 < 17);
        if (hn) load_chunk(c + 1, sbase + ((c + 1) & 1) * V_BUF);
        if (hn) cp_wait1(); else cp_wait0();
        __syncthreads();

        const uint32_t Ab = sbase + (c & 1) * V_BUF;
        #pragma unroll
        for (int ks = 0; ks < 4; ++ks) {
            uint32_t a[2][4];
            #pragma unroll
            for (int mt = 0; mt < 2; ++mt) {
                uint32_t off = SWZ((uint32_t)((m0w + mt * 16 + (lane & 15)) * 128
                                              + ks * 32 + (lane >> 4) * 16));
                ldsm4(a[mt], Ab + V_A + off);
            }
            uint32_t b[16];
            #pragma unroll
            for (int p = 0; p < 4; ++p) {
                uint32_t off = SWZ((uint32_t)((p * 16 + (lane & 7) + ((lane >> 4) & 1) * 8) * 128
                                              + ks * 32 + ((lane >> 3) & 1) * 16));
                ldsm4(&b[p * 4], Ab + V_B + off);
            }
            #pragma unroll
            for (int mt = 0; mt < 2; ++mt)
                #pragma unroll
                for (int nt = 0; nt < 8; ++nt)
                    mma_f16(C[mt][nt], a[mt], &b[(nt >> 1) * 4 + (nt & 1) * 2]);
        }
        __syncthreads();
    }

    const int n = ng >> 3, h = ng & 7;
    #pragma unroll
    for (int mt = 0; mt < 2; ++mt) {
        int qb = qt * 256 + m0w + mt * 16 + (lane >> 2);
        #pragma unroll
        for (int nt = 0; nt < 8; ++nt) {
            int dcol = nt * 8 + (lane & 3) * 2;
            #pragma unroll
            for (int hf = 0; hf < 2; ++hf) {
                int q = qb + hf * 8;
                size_t o = ((size_t)(n * TT + q)) * 512 + h * 64 + dcol;
                *(__half2*)(g_ctx + o) =
                    __floats2half2_rn(C[mt][nt][hf * 2 + 0], C[mt][nt][hf * 2 + 1]);
            }
        }
    }
}

// ------------------------- LayerNorm (warp per row) -------------------------
__global__ void __launch_bounds__(256) ln_kernel(
                          const float* __restrict__ gamma,
                          const float* __restrict__ beta,
                          float* __restrict__ out) {
    const int lane = threadIdx.x & 31, wid = threadIdx.x >> 5;
    const int r = blockIdx.x * 8 + wid;
    const float* in = g_t2 + (size_t)r * EE;

    float4 v[4];
    float s = 0.f;
    #pragma unroll
    for (int i = 0; i < 4; ++i) {
        v[i] = *(const float4*)(in + i * 128 + lane * 4);
        s += v[i].x + v[i].y + v[i].z + v[i].w;
    }
    #pragma unroll
    for (int o = 16; o; o >>= 1) s += __shfl_xor_sync(0xffffffffu, s, o);
    float mu = s * (1.f / EE);

    float vs = 0.f;
    #pragma unroll
    for (int i = 0; i < 4; ++i) {
        float dx = v[i].x - mu, dy = v[i].y - mu, dz = v[i].z - mu, dw = v[i].w - mu;
        vs += dx * dx + dy * dy + dz * dz + dw * dw;
    }
    #pragma unroll
    for (int o = 16; o; o >>= 1) vs += __shfl_xor_sync(0xffffffffu, vs, o);
    float inv = rsqrtf(vs * (1.f / EE) + 1e-5f);

    #pragma unroll
    for (int i = 0; i < 4; ++i) {
        int col = i * 128 + lane * 4;
        float4 g = *(const float4*)(gamma + col);
        float4 b = *(const float4*)(beta + col);
        float4 o;
        o.x = (v[i].x - mu) * inv * g.x + b.x;
        o.y = (v[i].y - mu) * inv * g.y + b.y;
        o.z = (v[i].z - mu) * inv * g.z + b.z;
        o.w = (v[i].w - mu) * inv * g.w + b.w;
        *(float4*)(out + (size_t)r * EE + col) = o;
    }
}

// ------------------------------ launcher -----------------------------------
extern "C" void kernel_launch(void* const* d_in, const int* in_sizes, int n_in,
                              void* d_out, int out_size) {
    const float* x        = (const float*)d_in[0];
    const int*   seq_mask = (const int*)  d_in[1];
    const float* Wq       = (const float*)d_in[2];
    const float* Wk       = (const float*)d_in[3];
    const float* Wv       = (const float*)d_in[4];
    const float* Wo       = (const float*)d_in[5];
    const float* bo       = (const float*)d_in[6];
    const float* pre_th   = (const float*)d_in[7];
    const float* post_th  = (const float*)d_in[8];
    const float* pk       = (const float*)d_in[9];
    const float* pv       = (const float*)d_in[10];
    const float* c1W      = (const float*)d_in[11];
    const float* c1b      = (const float*)d_in[12];
    const float* c2W      = (const float*)d_in[13];
    const float* c2b      = (const float*)d_in[14];
    const float* ln_g     = (const float*)d_in[15];
    const float* ln_b     = (const float*)d_in[16];
    float* out = (float*)d_out;

    __half *pWo, *pC1, *pC2, *pCtx, *pH, *pT1;
    float *pT2;
    cudaGetSymbolAddress((void**)&pWo,  g_Wo);
    cudaGetSymbolAddress((void**)&pC1,  g_c1);
    cudaGetSymbolAddress((void**)&pC2,  g_c2);
    cudaGetSymbolAddress((void**)&pCtx, g_ctx);
    cudaGetSymbolAddress((void**)&pH,   g_h);
    cudaGetSymbolAddress((void**)&pT1,  g_t1);
    cudaGetSymbolAddress((void**)&pT2,  g_t2);

    cudaFuncSetAttribute(gemm_hmma_kernel,
                         cudaFuncAttributeMaxDynamicSharedMemorySize, GEMM_SMEM);
    cudaFuncSetAttribute(energy_hmma_kernel,
                         cudaFuncAttributeMaxDynamicSharedMemorySize, EGY_SMEM);
    cudaFuncSetAttribute(av_hmma_kernel,
                         cudaFuncAttributeMaxDynamicSharedMemorySize, AV_SMEM);
    cudaFuncSetAttribute(qkv_hmma_kernel,
                         cudaFuncAttributeMaxDynamicSharedMemorySize, QKV_SMEM);

    wo_convert<<<1024, 256>>>(Wo, pWo);
    conv_w_convert<<<3072, 256>>>(c1W, pC1);
    conv_w_convert<<<3072, 256>>>(c2W, pC2);

    qkv_hmma_kernel<<<dim3(64, 8), 256, QKV_SMEM>>>(x, Wq, Wk, Wv);
    persist_pad_kernel<<<2816, 256>>>(pk, pv);

    energy_hmma_kernel<<<dim3(8, 64), 256, EGY_SMEM>>>();
    softmax_kernel<<<8192, 256>>>(pre_th, post_th, seq_mask);
    av_hmma_kernel<<<dim3(4, 64), 256, AV_SMEM>>>();

    gemm_hmma_kernel<<<dim3(64, 4), 256, GEMM_SMEM>>>(
        0, 8, pCtx, pWo, bo, x, nullptr, seq_mask, pH);
    gemm_hmma_kernel<<<dim3(64, 4), 256, GEMM_SMEM>>>(
        1, 24, pH, pC1, c1b, nullptr, nullptr, seq_mask, pT1);
    gemm_hmma_kernel<<<dim3(64, 4), 256, GEMM_SMEM>>>(
        2, 24, pT1, pC2, c2b, nullptr, pH, seq_mask, pT2);

    ln_kernel<<<1024, 256>>>(ln_g, ln_b, out);
}